// round 10
// baseline (speedup 1.0000x reference)
#include <cuda_runtime.h>
#include <cuda_bf16.h>
#include <math.h>
#include <cstdint>

#define B_ 4
#define T_ 8
#define C_ 128
#define HW_ 9216
#define NBT 32
#define NCHUNK 72
#define CHUNK 16384
#define TILEP 32
#define NTILE 288

typedef unsigned long long ull;
typedef unsigned int u32;

__device__ __forceinline__ ull pack2(float a, float b) {
    ull r; asm("mov.b64 %0,{%1,%2};" : "=l"(r) : "f"(a), "f"(b)); return r;
}
__device__ __forceinline__ void unpack2(ull v, float& a, float& b) {
    asm("mov.b64 {%0,%1},%2;" : "=f"(a), "=f"(b) : "l"(v));
}
__device__ __forceinline__ ull fma2(ull a, ull b, ull c) {
    ull d; asm("fma.rn.f32x2 %0,%1,%2,%3;" : "=l"(d) : "l"(a), "l"(b), "l"(c)); return d;
}
__device__ __forceinline__ ull mul2(ull a, ull b) {
    ull d; asm("mul.rn.f32x2 %0,%1,%2;" : "=l"(d) : "l"(a), "l"(b)); return d;
}

// hi/lo bf16 split of two floats -> two b32 (low half = first element)
__device__ __forceinline__ void split_store(float v0, float v1, u32* H, u32* L, int idx) {
    __nv_bfloat16 h0 = __float2bfloat16(v0);
    __nv_bfloat16 h1 = __float2bfloat16(v1);
    float r0 = v0 - __bfloat162float(h0);
    float r1 = v1 - __bfloat162float(h1);
    __nv_bfloat162 hh; hh.x = h0; hh.y = h1;
    __nv_bfloat162 llv; llv.x = __float2bfloat16(r0); llv.y = __float2bfloat16(r1);
    H[idx] = *(u32*)&hh;
    L[idx] = *(u32*)&llv;
}
__device__ __forceinline__ void split_pair(float v0, float v1, u32& h, u32& l) {
    __nv_bfloat16 h0 = __float2bfloat16(v0);
    __nv_bfloat16 h1 = __float2bfloat16(v1);
    float r0 = v0 - __bfloat162float(h0);
    float r1 = v1 - __bfloat162float(h1);
    __nv_bfloat162 hh; hh.x = h0; hh.y = h1;
    __nv_bfloat162 llv; llv.x = __float2bfloat16(r0); llv.y = __float2bfloat16(r1);
    h = *(u32*)&hh; l = *(u32*)&llv;
}

// m16n8k16 row.col f32.bf16.bf16.f32
__device__ __forceinline__ void mma16816(float c[4], const u32 a[4], const u32 b[2]) {
    asm volatile("mma.sync.aligned.m16n8k16.row.col.f32.bf16.bf16.f32 "
                 "{%0,%1,%2,%3},{%4,%5,%6,%7},{%8,%9},{%0,%1,%2,%3};"
                 : "+f"(c[0]), "+f"(c[1]), "+f"(c[2]), "+f"(c[3])
                 : "r"(a[0]), "r"(a[1]), "r"(a[2]), "r"(a[3]), "r"(b[0]), "r"(b[1]));
}

// deterministic scratch
__device__ float g_psum[NBT * NCHUNK];
__device__ float g_psq [NBT * NCHUNK];
__device__ float g_A[NBT * C_];
__device__ float g_Bc[NBT * C_];
// fragment-order weights: [mat][plane hi/lo][w16][ks][lane][4 u32]
// plane = 8*8*32*4 = 8192 u32 ; mat = 16384 u32
__device__ u32 g_Wpk[4 * 16384];

// ---------------- Kernel 1: partial sums ----------------
__global__ __launch_bounds__(256) void reduce_kernel(const float* __restrict__ x,
                                                     const float* __restrict__ pos) {
    int bt = blockIdx.x / NCHUNK, chunk = blockIdx.x % NCHUNK, t = bt & (T_ - 1);
    const float4* x4 = (const float4*)(x + (size_t)bt * C_ * HW_);
    int base4 = chunk * (CHUNK / 4);
    float s = 0.f, sq = 0.f;
#pragma unroll
    for (int i = 0; i < 16; i++) {
        int e4 = base4 + i * 256 + threadIdx.x;
        int c = e4 / 2304;
        float pv = pos[t * C_ + c];
        float4 v = x4[e4];
        float a0 = v.x + pv, a1 = v.y + pv, a2 = v.z + pv, a3 = v.w + pv;
        s += (a0 + a1) + (a2 + a3);
        sq += (a0 * a0 + a1 * a1) + (a2 * a2 + a3 * a3);
    }
    __shared__ float ss[8], ssq[8];
#pragma unroll
    for (int o = 16; o; o >>= 1) {
        s += __shfl_down_sync(0xFFFFFFFFu, s, o);
        sq += __shfl_down_sync(0xFFFFFFFFu, sq, o);
    }
    int w = threadIdx.x >> 5;
    if ((threadIdx.x & 31) == 0) { ss[w] = s; ssq[w] = sq; }
    __syncthreads();
    if (threadIdx.x == 0) {
        float S = 0.f, SQ = 0.f;
#pragma unroll
        for (int i = 0; i < 8; i++) { S += ss[i]; SQ += ssq[i]; }
        g_psum[bt * NCHUNK + chunk] = S;
        g_psq [bt * NCHUNK + chunk] = SQ;
    }
}

// ---------------- Kernel 2: finalize ----------------
__global__ __launch_bounds__(256) void finalize_kernel(const float* __restrict__ pos,
                                                       const float* __restrict__ nw,
                                                       const float* __restrict__ nb) {
    __shared__ float sm[NBT], sr[NBT];
    int tid = threadIdx.x;
    if (tid < NBT) {
        float S = 0.f, SQ = 0.f;
        for (int i = 0; i < NCHUNK; i++) { S += g_psum[tid * NCHUNK + i]; SQ += g_psq[tid * NCHUNK + i]; }
        const float invN = 1.0f / (float)(C_ * HW_);
        float mean = S * invN;
        float var = SQ * invN - mean * mean;
        sm[tid] = mean;
        sr[tid] = rsqrtf(var + 1e-5f);
    }
    __syncthreads();
    for (int idx = tid; idx < NBT * C_; idx += 256) {
        int bt = idx >> 7, c = idx & 127, t = bt & (T_ - 1);
        float a = sr[bt] * nw[c];
        g_A[idx] = a;
        g_Bc[idx] = (pos[t * C_ + c] - sm[bt]) * a + nb[c];
    }
}

// ---------------- Kernel 2b: weight prep in fragment order ----------------
// one thread per (mat, w16, ks, lane): writes uint4 hi + uint4 lo
__global__ __launch_bounds__(256) void wprep_kernel(const float* __restrict__ qkv_w,
                                                    const float* __restrict__ proj_w) {
    int i = blockIdx.x * 256 + threadIdx.x;   // 0..8191
    int mat  = i >> 11;
    int rem  = i & 2047;
    int w16  = rem >> 8;
    int ks   = (rem >> 5) & 7;
    int lane = rem & 31;
    int g = lane >> 2, t = lane & 3;
    int r0 = w16 * 16 + g, r1 = r0 + 8;
    int kp0 = 8 * ks + t, kp1 = kp0 + 4;
    const float sc = 0.17677669529663687f;

    auto fetch = [&](int r, int c) -> float {
        if (mat == 0) return qkv_w[r * 128 + c];
        if (mat == 1) return qkv_w[(128 + c) * 128 + r] * sc;   // WkT (scaled)
        if (mat == 2) return qkv_w[(256 + r) * 128 + c];
        return proj_w[r * 128 + c];
    };

    u32 H[4], L[4];
    split_pair(fetch(r0, 2 * kp0), fetch(r0, 2 * kp0 + 1), H[0], L[0]);
    split_pair(fetch(r1, 2 * kp0), fetch(r1, 2 * kp0 + 1), H[1], L[1]);
    split_pair(fetch(r0, 2 * kp1), fetch(r0, 2 * kp1 + 1), H[2], L[2]);
    split_pair(fetch(r1, 2 * kp1), fetch(r1, 2 * kp1 + 1), H[3], L[3]);

    int base = mat * 16384 + ((w16 * 8 + ks) * 32 + lane) * 4;
    *(uint4*)(g_Wpk + base)        = make_uint4(H[0], H[1], H[2], H[3]);
    *(uint4*)(g_Wpk + 8192 + base) = make_uint4(L[0], L[1], L[2], L[3]);
}

// ---------------- Kernel 3: fused main with mma.sync GEMMs ----------------
#define PB 40               // B-tile pitch (b32): conflict-free
#define PD 33               // f32 scratch pitch
#define SM_B0H 0            // 2560
#define SM_B0L 2560         // 2560
#define SM_BIG 5120         // 20480: U f32 scratch pitch 33; then E B-tiles
#define SM_D   25600        // 4224 f32 scratch
#define SM_AB  29824        // 2048
#define SM_P   31872        // 1024
#define SMEM_FLOATS 32896
#define SMEM_BYTES (SMEM_FLOATS * 4)   // 131584

// compensated GEMM slice with fragment-order weights (vector LDG.128 per ks)
__device__ __forceinline__ void gemm_mma(const u32* __restrict__ Whi, const u32* __restrict__ Wlo,
                                         const u32* Bh, const u32* Bl,
                                         int w16, int lane, int g, int t,
                                         int ks0, int ksn, float acc[4][4]) {
#pragma unroll
    for (int ki = 0; ki < ksn; ki++) {
        int ks = ks0 + ki;
        int fi = ((w16 * 8 + ks) * 32 + lane) * 4;
        uint4 aH4 = *(const uint4*)(Whi + fi);
        uint4 aL4 = *(const uint4*)(Wlo + fi);
        u32 aH[4] = {aH4.x, aH4.y, aH4.z, aH4.w};
        u32 aL[4] = {aL4.x, aL4.y, aL4.z, aL4.w};
        int rB0 = (8 * ks + t) * PB + g;
        int rB1 = rB0 + 4 * PB;
#pragma unroll
        for (int nt = 0; nt < 4; nt++) {
            u32 bh[2] = {Bh[rB0 + 8 * nt], Bh[rB1 + 8 * nt]};
            u32 bl[2] = {Bl[rB0 + 8 * nt], Bl[rB1 + 8 * nt]};
            mma16816(acc[nt], aH, bh);
            mma16816(acc[nt], aL, bh);
            mma16816(acc[nt], aH, bl);
        }
    }
}

__global__ __launch_bounds__(256, 1) void main_kernel(const float* __restrict__ x,
                                                      float* __restrict__ out) {
    extern __shared__ float sm[];
    u32* sB0H = (u32*)(sm + SM_B0H);
    u32* sB0L = (u32*)(sm + SM_B0L);
    float* sBIG = sm + SM_BIG;
    float* sD  = sm + SM_D;
    float* sAB = sm + SM_AB;
    float* sP  = sm + SM_P;

    int b    = blockIdx.x / NTILE;
    int tile = blockIdx.x % NTILE;
    int hw0  = tile * TILEP;
    int tid  = threadIdx.x;
    int wid  = tid >> 5, lane = tid & 31;
    int g    = lane >> 2, t = lane & 3;
    int cld  = wid;
    int pld  = lane;
    int c0   = cld * 16;

    // stage affine tables
    for (int idx = tid; idx < 1024; idx += 256) {
        sAB[idx]        = g_A [b * 1024 + idx];
        sAB[1024 + idx] = g_Bc[b * 1024 + idx];
    }
    // raw x7 + t0 prefetch
    float xn[16], xr[16];
    {
        const float* xb7 = x + (size_t)(b * T_ + 7) * C_ * HW_;
        const float* xb0 = x + (size_t)(b * T_) * C_ * HW_;
#pragma unroll
        for (int j = 0; j < 16; j++) xn[j] = xb7[(c0 + j) * HW_ + hw0 + pld];
#pragma unroll
        for (int j = 0; j < 16; j++) xr[j] = xb0[(c0 + j) * HW_ + hw0 + pld];
    }
    __syncthreads();

    // normalize x7 in regs; pack B tile (slot0)
    {
        const float* As = sAB + 7 * 128;
        const float* Bs = sAB + 1024 + 7 * 128;
#pragma unroll
        for (int j = 0; j < 16; j++) xn[j] = xn[j] * As[c0 + j] + Bs[c0 + j];
#pragma unroll
        for (int k = 0; k < 8; k++)
            split_store(xn[2 * k], xn[2 * k + 1], sB0H, sB0L, (8 * cld + k) * PB + pld);
    }
    __syncthreads();

    // ---- Phase Q: Q[m][px] = Wq @ XN7 ----
    {
        float acc[4][4] = {};
        gemm_mma(g_Wpk, g_Wpk + 8192, sB0H, sB0L, wid, lane, g, t, 0, 8, acc);
#pragma unroll
        for (int nt = 0; nt < 4; nt++) {
            int base  = (16 * wid + g) * PD + 8 * nt + 2 * t;
            int base8 = base + 8 * PD;
            sD[base] = acc[nt][0]; sD[base + 1] = acc[nt][1];
            sD[base8] = acc[nt][2]; sD[base8 + 1] = acc[nt][3];
        }
    }
    __syncthreads();
    // repack Q -> slot0 hi/lo
#pragma unroll
    for (int j = 0; j < 8; j++) {
        int k2 = (tid >> 5) + 8 * j, px = tid & 31;
        split_store(sD[(2 * k2) * PD + px], sD[(2 * k2 + 1) * PD + px], sB0H, sB0L, k2 * PB + px);
    }
    __syncthreads();

    // ---- Phase U: per head h, U_h[c][px] (ks {2h, 2h+1}) ----
    {
        const u32* Whi = g_Wpk + 16384;
        const u32* Wlo = g_Wpk + 16384 + 8192;
#pragma unroll
        for (int h = 0; h < 4; h++) {
            float acc[4][4] = {};
            gemm_mma(Whi, Wlo, sB0H, sB0L, wid, lane, g, t, 2 * h, 2, acc);
            float* uD = sBIG + h * 4224;
#pragma unroll
            for (int nt = 0; nt < 4; nt++) {
                int base  = (16 * wid + g) * PD + 8 * nt + 2 * t;
                int base8 = base + 8 * PD;
                uD[base] = acc[nt][0]; uD[base + 1] = acc[nt][1];
                uD[base8] = acc[nt][2]; uD[base8 + 1] = acc[nt][3];
            }
        }
    }
    __syncthreads();

    // load U into regs (adjacent c-pairs)
    ull uP[4][8];
#pragma unroll
    for (int h = 0; h < 4; h++)
#pragma unroll
        for (int k = 0; k < 8; k++)
            uP[h][k] = pack2(sBIG[h * 4224 + (c0 + 2 * k) * PD + pld],
                             sBIG[h * 4224 + (c0 + 2 * k + 1) * PD + pld]);

    ull xnP[8];
#pragma unroll
    for (int k = 0; k < 8; k++) xnP[k] = pack2(xn[2 * k], xn[2 * k + 1]);

    // ---- register-resident online softmax + xbar ----
    ull xbarP[4][8];
#pragma unroll
    for (int h = 0; h < 4; h++)
#pragma unroll
        for (int k = 0; k < 8; k++) xbarP[h][k] = 0ull;
    float m_run[4] = {-1e30f, -1e30f, -1e30f, -1e30f};
    float s_run[4] = {0.f, 0.f, 0.f, 0.f};

    for (int it = 0; it < T_; it++) {
        int s = (it == 0) ? (T_ - 1) : (it - 1);
        if (it > 0) {
            const float* As = sAB + s * 128;
            const float* Bs = sAB + 1024 + s * 128;
#pragma unroll
            for (int k = 0; k < 8; k++) {
                float a0 = xr[2 * k] * As[c0 + 2 * k] + Bs[c0 + 2 * k];
                float a1 = xr[2 * k + 1] * As[c0 + 2 * k + 1] + Bs[c0 + 2 * k + 1];
                xnP[k] = pack2(a0, a1);
            }
        }
        if (it >= 1 && it < T_ - 1) {
            const float* xb = x + (size_t)(b * T_ + it) * C_ * HW_;
#pragma unroll
            for (int j = 0; j < 16; j++) xr[j] = xb[(c0 + j) * HW_ + hw0 + pld];
        }
        ull lg[4] = {0ull, 0ull, 0ull, 0ull};
#pragma unroll
        for (int k = 0; k < 8; k++) {
            lg[0] = fma2(xnP[k], uP[0][k], lg[0]);
            lg[1] = fma2(xnP[k], uP[1][k], lg[1]);
            lg[2] = fma2(xnP[k], uP[2][k], lg[2]);
            lg[3] = fma2(xnP[k], uP[3][k], lg[3]);
        }
        float4 part;
        { float lo, hi;
          unpack2(lg[0], lo, hi); part.x = lo + hi;
          unpack2(lg[1], lo, hi); part.y = lo + hi;
          unpack2(lg[2], lo, hi); part.z = lo + hi;
          unpack2(lg[3], lo, hi); part.w = lo + hi; }
        *(float4*)(sP + (cld * 32 + pld) * 4) = part;
        __syncthreads();
        float L[4] = {0.f, 0.f, 0.f, 0.f};
#pragma unroll
        for (int k = 0; k < 8; k++) {
            float4 v = *(const float4*)(sP + (k * 32 + pld) * 4);
            L[0] += v.x; L[1] += v.y; L[2] += v.z; L[3] += v.w;
        }
        __syncthreads();
#pragma unroll
        for (int h = 0; h < 4; h++) {
            float mn = fmaxf(m_run[h], L[h]);
            float corr = __expf(m_run[h] - mn);
            float e = __expf(L[h] - mn);
            s_run[h] = s_run[h] * corr + e;
            m_run[h] = mn;
            ull cP = pack2(corr, corr), eP = pack2(e, e);
#pragma unroll
            for (int k = 0; k < 8; k++)
                xbarP[h][k] = fma2(eP, xnP[k], mul2(cP, xbarP[h][k]));
        }
    }
    __syncthreads();

    // normalize xbar -> E B-tiles (per head hi/lo planes)
#pragma unroll
    for (int h = 0; h < 4; h++) {
        float inv = 1.0f / s_run[h];
        ull iP = pack2(inv, inv);
        u32* EH = (u32*)(sBIG + h * 5120);
        u32* EL = (u32*)(sBIG + h * 5120 + 2560);
#pragma unroll
        for (int k = 0; k < 8; k++) {
            float v0, v1;
            unpack2(mul2(iP, xbarP[h][k]), v0, v1);
            split_store(v0, v1, EH, EL, (8 * cld + k) * PB + pld);
        }
    }
    __syncthreads();

    // ---- Phase E: warp w -> head h=w>>1; Out rows 16w..16w+15 ----
    {
        int h = wid >> 1;
        const u32* Whi = g_Wpk + 2 * 16384;
        const u32* Wlo = g_Wpk + 2 * 16384 + 8192;
        u32* EH = (u32*)(sBIG + h * 5120);
        u32* EL = (u32*)(sBIG + h * 5120 + 2560);
        float acc[4][4] = {};
        gemm_mma(Whi, Wlo, EH, EL, wid, lane, g, t, 0, 8, acc);
#pragma unroll
        for (int nt = 0; nt < 4; nt++) {
            int base  = (16 * wid + g) * PD + 8 * nt + 2 * t;
            int base8 = base + 8 * PD;
            sD[base] = acc[nt][0]; sD[base + 1] = acc[nt][1];
            sD[base8] = acc[nt][2]; sD[base8 + 1] = acc[nt][3];
        }
    }
    __syncthreads();
    // repack Out -> slot0
#pragma unroll
    for (int j = 0; j < 8; j++) {
        int k2 = (tid >> 5) + 8 * j, px = tid & 31;
        split_store(sD[(2 * k2) * PD + px], sD[(2 * k2 + 1) * PD + px], sB0H, sB0L, k2 * PB + px);
    }
    __syncthreads();

    // ---- Phase F: y = proj @ Out -> gmem direct ----
    {
        const u32* Whi = g_Wpk + 3 * 16384;
        const u32* Wlo = g_Wpk + 3 * 16384 + 8192;
        float acc[4][4] = {};
        gemm_mma(Whi, Wlo, sB0H, sB0L, wid, lane, g, t, 0, 8, acc);
        float* o0 = out + ((size_t)b * C_ + 16 * wid + g) * HW_ + hw0;
        float* o8 = out + ((size_t)b * C_ + 16 * wid + g + 8) * HW_ + hw0;
#pragma unroll
        for (int nt = 0; nt < 4; nt++) {
            int px = 8 * nt + 2 * t;
            *(float2*)(o0 + px) = make_float2(acc[nt][0], acc[nt][1]);
            *(float2*)(o8 + px) = make_float2(acc[nt][2], acc[nt][3]);
        }
    }
}

extern "C" void kernel_launch(void* const* d_in, const int* in_sizes, int n_in,
                              void* d_out, int out_size) {
    const float* x    = (const float*)d_in[0];
    const float* pos  = (const float*)d_in[1];
    const float* nw   = (const float*)d_in[2];
    const float* nb   = (const float*)d_in[3];
    const float* qkvw = (const float*)d_in[4];
    const float* pw   = (const float*)d_in[5];
    float* out = (float*)d_out;

    reduce_kernel<<<NBT * NCHUNK, 256>>>(x, pos);
    finalize_kernel<<<1, 256>>>(pos, nw, nb);
    wprep_kernel<<<32, 256>>>(qkvw, pw);
    cudaFuncSetAttribute(main_kernel, cudaFuncAttributeMaxDynamicSharedMemorySize, SMEM_BYTES);
    main_kernel<<<B_ * NTILE, 256, SMEM_BYTES>>>(x, out);
}

// round 11
// speedup vs baseline: 1.4210x; 1.4210x over previous
#include <cuda_runtime.h>
#include <cuda_bf16.h>
#include <math.h>
#include <cstdint>

#define B_ 4
#define T_ 8
#define C_ 128
#define HW_ 9216
#define NBT 32
#define NCHUNK 72
#define CHUNK 16384
#define TILEP 32
#define NTILE 288

typedef unsigned long long ull;
typedef unsigned int u32;

__device__ __forceinline__ ull pack2(float a, float b) {
    ull r; asm("mov.b64 %0,{%1,%2};" : "=l"(r) : "f"(a), "f"(b)); return r;
}
__device__ __forceinline__ void unpack2(ull v, float& a, float& b) {
    asm("mov.b64 {%0,%1},%2;" : "=f"(a), "=f"(b) : "l"(v));
}
__device__ __forceinline__ ull fma2(ull a, ull b, ull c) {
    ull d; asm("fma.rn.f32x2 %0,%1,%2,%3;" : "=l"(d) : "l"(a), "l"(b), "l"(c)); return d;
}
__device__ __forceinline__ ull mul2(ull a, ull b) {
    ull d; asm("mul.rn.f32x2 %0,%1,%2;" : "=l"(d) : "l"(a), "l"(b)); return d;
}

// hi/lo bf16 split of two floats -> two b32 planes
__device__ __forceinline__ void split_store(float v0, float v1, u32* H, u32* L, int idx) {
    __nv_bfloat16 h0 = __float2bfloat16(v0);
    __nv_bfloat16 h1 = __float2bfloat16(v1);
    float r0 = v0 - __bfloat162float(h0);
    float r1 = v1 - __bfloat162float(h1);
    __nv_bfloat162 hh; hh.x = h0; hh.y = h1;
    __nv_bfloat162 llv; llv.x = __float2bfloat16(r0); llv.y = __float2bfloat16(r1);
    H[idx] = *(u32*)&hh;
    L[idx] = *(u32*)&llv;
}
__device__ __forceinline__ void split_pair(float v0, float v1, u32& h, u32& l) {
    __nv_bfloat16 h0 = __float2bfloat16(v0);
    __nv_bfloat16 h1 = __float2bfloat16(v1);
    float r0 = v0 - __bfloat162float(h0);
    float r1 = v1 - __bfloat162float(h1);
    __nv_bfloat162 hh; hh.x = h0; hh.y = h1;
    __nv_bfloat162 llv; llv.x = __float2bfloat16(r0); llv.y = __float2bfloat16(r1);
    h = *(u32*)&hh; l = *(u32*)&llv;
}

// m16n8k16 row.col f32.bf16.bf16.f32
__device__ __forceinline__ void mma16816(float c[4], const u32 a[4], const u32 b[2]) {
    asm volatile("mma.sync.aligned.m16n8k16.row.col.f32.bf16.bf16.f32 "
                 "{%0,%1,%2,%3},{%4,%5,%6,%7},{%8,%9},{%0,%1,%2,%3};"
                 : "+f"(c[0]), "+f"(c[1]), "+f"(c[2]), "+f"(c[3])
                 : "r"(a[0]), "r"(a[1]), "r"(a[2]), "r"(a[3]), "r"(b[0]), "r"(b[1]));
}

// deterministic scratch
__device__ float g_psum[NBT * NCHUNK];
__device__ float g_psq [NBT * NCHUNK];
__device__ float g_A[NBT * C_];
__device__ float g_Bc[NBT * C_];
// fragment-order weights: [mat][plane hi/lo][w16][ks][lane][4 u32]
__device__ u32 g_Wpk[4 * 16384];

// ---------------- Kernel 1: partial sums ----------------
__global__ __launch_bounds__(256) void reduce_kernel(const float* __restrict__ x,
                                                     const float* __restrict__ pos) {
    int bt = blockIdx.x / NCHUNK, chunk = blockIdx.x % NCHUNK, t = bt & (T_ - 1);
    const float4* x4 = (const float4*)(x + (size_t)bt * C_ * HW_);
    int base4 = chunk * (CHUNK / 4);
    float s = 0.f, sq = 0.f;
#pragma unroll
    for (int i = 0; i < 16; i++) {
        int e4 = base4 + i * 256 + threadIdx.x;
        int c = e4 / 2304;
        float pv = pos[t * C_ + c];
        float4 v = x4[e4];
        float a0 = v.x + pv, a1 = v.y + pv, a2 = v.z + pv, a3 = v.w + pv;
        s += (a0 + a1) + (a2 + a3);
        sq += (a0 * a0 + a1 * a1) + (a2 * a2 + a3 * a3);
    }
    __shared__ float ss[8], ssq[8];
#pragma unroll
    for (int o = 16; o; o >>= 1) {
        s += __shfl_down_sync(0xFFFFFFFFu, s, o);
        sq += __shfl_down_sync(0xFFFFFFFFu, sq, o);
    }
    int w = threadIdx.x >> 5;
    if ((threadIdx.x & 31) == 0) { ss[w] = s; ssq[w] = sq; }
    __syncthreads();
    if (threadIdx.x == 0) {
        float S = 0.f, SQ = 0.f;
#pragma unroll
        for (int i = 0; i < 8; i++) { S += ss[i]; SQ += ssq[i]; }
        g_psum[bt * NCHUNK + chunk] = S;
        g_psq [bt * NCHUNK + chunk] = SQ;
    }
}

// ---------------- Kernel 2: finalize ----------------
__global__ __launch_bounds__(256) void finalize_kernel(const float* __restrict__ pos,
                                                       const float* __restrict__ nw,
                                                       const float* __restrict__ nb) {
    __shared__ float sm[NBT], sr[NBT];
    int tid = threadIdx.x;
    if (tid < NBT) {
        float S = 0.f, SQ = 0.f;
        for (int i = 0; i < NCHUNK; i++) { S += g_psum[tid * NCHUNK + i]; SQ += g_psq[tid * NCHUNK + i]; }
        const float invN = 1.0f / (float)(C_ * HW_);
        float mean = S * invN;
        float var = SQ * invN - mean * mean;
        sm[tid] = mean;
        sr[tid] = rsqrtf(var + 1e-5f);
    }
    __syncthreads();
    for (int idx = tid; idx < NBT * C_; idx += 256) {
        int bt = idx >> 7, c = idx & 127, t = bt & (T_ - 1);
        float a = sr[bt] * nw[c];
        g_A[idx] = a;
        g_Bc[idx] = (pos[t * C_ + c] - sm[bt]) * a + nb[c];
    }
}

// ---------------- Kernel 2b: weight prep in fragment order ----------------
__global__ __launch_bounds__(256) void wprep_kernel(const float* __restrict__ qkv_w,
                                                    const float* __restrict__ proj_w) {
    int i = blockIdx.x * 256 + threadIdx.x;   // 0..8191
    int mat  = i >> 11;
    int rem  = i & 2047;
    int w16  = rem >> 8;
    int ks   = (rem >> 5) & 7;
    int lane = rem & 31;
    int g = lane >> 2, t = lane & 3;
    int r0 = w16 * 16 + g, r1 = r0 + 8;
    int kp0 = 8 * ks + t, kp1 = kp0 + 4;
    const float sc = 0.17677669529663687f;

    auto fetch = [&](int r, int c) -> float {
        if (mat == 0) return qkv_w[r * 128 + c];
        if (mat == 1) return qkv_w[(128 + c) * 128 + r] * sc;   // WkT (scaled)
        if (mat == 2) return qkv_w[(256 + r) * 128 + c];
        return proj_w[r * 128 + c];
    };

    u32 H[4], L[4];
    split_pair(fetch(r0, 2 * kp0), fetch(r0, 2 * kp0 + 1), H[0], L[0]);
    split_pair(fetch(r1, 2 * kp0), fetch(r1, 2 * kp0 + 1), H[1], L[1]);
    split_pair(fetch(r0, 2 * kp1), fetch(r0, 2 * kp1 + 1), H[2], L[2]);
    split_pair(fetch(r1, 2 * kp1), fetch(r1, 2 * kp1 + 1), H[3], L[3]);

    int base = mat * 16384 + ((w16 * 8 + ks) * 32 + lane) * 4;
    *(uint4*)(g_Wpk + base)        = make_uint4(H[0], H[1], H[2], H[3]);
    *(uint4*)(g_Wpk + 8192 + base) = make_uint4(L[0], L[1], L[2], L[3]);
}

// ---------------- Kernel 3: fused main ----------------
#define PB 40               // B-tile pitch (b32): conflict-free
// float-unit layout:
// [0,5120)      slot0 tile (hi 2560 / lo 2560); sP overlays [0,1024) during loop
// [5120,10240)  slot1 tile (Q output); later E tileA
// [10240,26624) sUP (8192 ull fp32-pairs); later E tileB overlaps [10240,15360)
// [26624,28672) affine AB
#define SM_S1   5120
#define SM_UP   10240
#define SM_AB   26624
#define SMEM_FLOATS 28672
#define SMEM_BYTES (SMEM_FLOATS * 4)   // 114688 = 112KB

// compensated GEMM slice with fragment-order weights
__device__ __forceinline__ void gemm_mma(const u32* __restrict__ Whi, const u32* __restrict__ Wlo,
                                         const u32* Bh, const u32* Bl,
                                         int w16, int lane, int g, int t,
                                         int ks0, int ksn, float acc[4][4]) {
#pragma unroll
    for (int ki = 0; ki < ksn; ki++) {
        int ks = ks0 + ki;
        int fi = ((w16 * 8 + ks) * 32 + lane) * 4;
        uint4 aH4 = *(const uint4*)(Whi + fi);
        uint4 aL4 = *(const uint4*)(Wlo + fi);
        u32 aH[4] = {aH4.x, aH4.y, aH4.z, aH4.w};
        u32 aL[4] = {aL4.x, aL4.y, aL4.z, aL4.w};
        int rB0 = (8 * ks + t) * PB + g;
        int rB1 = rB0 + 4 * PB;
#pragma unroll
        for (int nt = 0; nt < 4; nt++) {
            u32 bh[2] = {Bh[rB0 + 8 * nt], Bh[rB1 + 8 * nt]};
            u32 bl[2] = {Bl[rB0 + 8 * nt], Bl[rB1 + 8 * nt]};
            mma16816(acc[nt], aH, bh);
            mma16816(acc[nt], aL, bh);
            mma16816(acc[nt], aH, bl);
        }
    }
}

// shuffle-pair direct store of D fragment into a bf16 hi/lo B-tile (k2 = row/2)
__device__ __forceinline__ void frag_store_tile(const float acc[4][4], int g, int t,
                                                u32* H, u32* L, int w16) {
    int k2 = 8 * w16 + (g >> 1);
#pragma unroll
    for (int nt = 0; nt < 4; nt++) {
        float o0 = __shfl_xor_sync(0xFFFFFFFFu, acc[nt][0], 4);
        float o1 = __shfl_xor_sync(0xFFFFFFFFu, acc[nt][1], 4);
        float o2 = __shfl_xor_sync(0xFFFFFFFFu, acc[nt][2], 4);
        float o3 = __shfl_xor_sync(0xFFFFFFFFu, acc[nt][3], 4);
        int col = 8 * nt + 2 * t + (g & 1);
        float v0, v1, u0, u1;
        if ((g & 1) == 0) { v0 = acc[nt][0]; v1 = o0; u0 = acc[nt][2]; u1 = o2; }
        else              { v0 = o1; v1 = acc[nt][1]; u0 = o3; u1 = acc[nt][3]; }
        split_store(v0, v1, H, L, k2 * PB + col);
        split_store(u0, u1, H, L, (k2 + 4) * PB + col);
    }
}

// shuffle-pair direct store of D fragment into fp32-pair ull array (U)
__device__ __forceinline__ void frag_store_up(const float acc[4][4], int g, int t,
                                              ull* UP, int rowBase) {
    int c2 = g >> 1;
#pragma unroll
    for (int nt = 0; nt < 4; nt++) {
        float o0 = __shfl_xor_sync(0xFFFFFFFFu, acc[nt][0], 4);
        float o1 = __shfl_xor_sync(0xFFFFFFFFu, acc[nt][1], 4);
        float o2 = __shfl_xor_sync(0xFFFFFFFFu, acc[nt][2], 4);
        float o3 = __shfl_xor_sync(0xFFFFFFFFu, acc[nt][3], 4);
        int col = 8 * nt + 2 * t + (g & 1);
        ull lo, hi;
        if ((g & 1) == 0) { lo = pack2(acc[nt][0], o0); hi = pack2(acc[nt][2], o2); }
        else              { lo = pack2(o1, acc[nt][1]); hi = pack2(o3, acc[nt][3]); }
        UP[(rowBase + c2) * 32 + col]     = lo;
        UP[(rowBase + c2 + 4) * 32 + col] = hi;
    }
}

__global__ __launch_bounds__(256, 2) void main_kernel(const float* __restrict__ x,
                                                      float* __restrict__ out) {
    extern __shared__ float sm[];
    u32* sT0H = (u32*)sm;
    u32* sT0L = sT0H + 2560;
    u32* sS1H = (u32*)(sm + SM_S1);
    u32* sS1L = sS1H + 2560;
    ull* UPa  = (ull*)(sm + SM_UP);
    float* sP  = sm;                 // overlay, loop-only
    float* sAB = sm + SM_AB;

    int b    = blockIdx.x / NTILE;
    int tile = blockIdx.x % NTILE;
    int hw0  = tile * TILEP;
    int tid  = threadIdx.x;
    int wid  = tid >> 5, lane = tid & 31;
    int g    = lane >> 2, t = lane & 3;
    int cld  = wid;
    int pld  = lane;
    int c0   = cld * 16;

    // stage affine tables
    for (int idx = tid; idx < 1024; idx += 256) {
        sAB[idx]        = g_A [b * 1024 + idx];
        sAB[1024 + idx] = g_Bc[b * 1024 + idx];
    }
    // raw x7 + t0 prefetch
    float xn[16], xr[16];
    {
        const float* xb7 = x + (size_t)(b * T_ + 7) * C_ * HW_;
        const float* xb0 = x + (size_t)(b * T_) * C_ * HW_;
#pragma unroll
        for (int j = 0; j < 16; j++) xn[j] = xb7[(c0 + j) * HW_ + hw0 + pld];
#pragma unroll
        for (int j = 0; j < 16; j++) xr[j] = xb0[(c0 + j) * HW_ + hw0 + pld];
    }
    __syncthreads();

    // normalize x7; pack slot0 B tile
    {
        const float* As = sAB + 7 * 128;
        const float* Bs = sAB + 1024 + 7 * 128;
#pragma unroll
        for (int j = 0; j < 16; j++) xn[j] = xn[j] * As[c0 + j] + Bs[c0 + j];
#pragma unroll
        for (int k = 0; k < 8; k++)
            split_store(xn[2 * k], xn[2 * k + 1], sT0H, sT0L, (8 * cld + k) * PB + pld);
    }
    __syncthreads();

    // ---- Phase Q: Wq @ XN7 -> slot1 tile (direct shuffle-pair store) ----
    {
        float acc[4][4] = {};
        gemm_mma(g_Wpk, g_Wpk + 8192, sT0H, sT0L, wid, lane, g, t, 0, 8, acc);
        frag_store_tile(acc, g, t, sS1H, sS1L, wid);
    }
    __syncthreads();

    // ---- Phase U: per head h (ks {2h,2h+1}) -> sUP fp32-pairs ----
    {
        const u32* Whi = g_Wpk + 16384;
        const u32* Wlo = g_Wpk + 16384 + 8192;
#pragma unroll
        for (int h = 0; h < 4; h++) {
            float acc[4][4] = {};
            gemm_mma(Whi, Wlo, sS1H, sS1L, wid, lane, g, t, 2 * h, 2, acc);
            frag_store_up(acc, g, t, UPa, h * 64 + 8 * wid);
        }
    }
    __syncthreads();

    // ---- register-resident online softmax + xbar (U read from smem) ----
    ull xnP[8];
#pragma unroll
    for (int k = 0; k < 8; k++) xnP[k] = pack2(xn[2 * k], xn[2 * k + 1]);

    ull xbarP[4][8];
#pragma unroll
    for (int h = 0; h < 4; h++)
#pragma unroll
        for (int k = 0; k < 8; k++) xbarP[h][k] = 0ull;
    float m_run[4] = {-1e30f, -1e30f, -1e30f, -1e30f};
    float s_run[4] = {0.f, 0.f, 0.f, 0.f};

    const ull* upb = UPa + (8 * cld) * 32 + pld;   // + h*2048 + k*32

    for (int it = 0; it < T_; it++) {
        int s = (it == 0) ? (T_ - 1) : (it - 1);
        if (it > 0) {
            const float* As = sAB + s * 128;
            const float* Bs = sAB + 1024 + s * 128;
#pragma unroll
            for (int k = 0; k < 8; k++) {
                float a0 = xr[2 * k] * As[c0 + 2 * k] + Bs[c0 + 2 * k];
                float a1 = xr[2 * k + 1] * As[c0 + 2 * k + 1] + Bs[c0 + 2 * k + 1];
                xnP[k] = pack2(a0, a1);
            }
        }
        if (it >= 1 && it < T_ - 1) {
            const float* xb = x + (size_t)(b * T_ + it) * C_ * HW_;
#pragma unroll
            for (int j = 0; j < 16; j++) xr[j] = xb[(c0 + j) * HW_ + hw0 + pld];
        }
        ull lg[4] = {0ull, 0ull, 0ull, 0ull};
#pragma unroll
        for (int k = 0; k < 8; k++) {
            ull xv = xnP[k];
            lg[0] = fma2(xv, upb[0 * 2048 + k * 32], lg[0]);
            lg[1] = fma2(xv, upb[1 * 2048 + k * 32], lg[1]);
            lg[2] = fma2(xv, upb[2 * 2048 + k * 32], lg[2]);
            lg[3] = fma2(xv, upb[3 * 2048 + k * 32], lg[3]);
        }
        float4 part;
        { float lo, hi;
          unpack2(lg[0], lo, hi); part.x = lo + hi;
          unpack2(lg[1], lo, hi); part.y = lo + hi;
          unpack2(lg[2], lo, hi); part.z = lo + hi;
          unpack2(lg[3], lo, hi); part.w = lo + hi; }
        *(float4*)(sP + (cld * 32 + pld) * 4) = part;
        __syncthreads();
        float L[4] = {0.f, 0.f, 0.f, 0.f};
#pragma unroll
        for (int k = 0; k < 8; k++) {
            float4 v = *(const float4*)(sP + (k * 32 + pld) * 4);
            L[0] += v.x; L[1] += v.y; L[2] += v.z; L[3] += v.w;
        }
        __syncthreads();
#pragma unroll
        for (int h = 0; h < 4; h++) {
            float mn = fmaxf(m_run[h], L[h]);
            float corr = __expf(m_run[h] - mn);
            float e = __expf(L[h] - mn);
            s_run[h] = s_run[h] * corr + e;
            m_run[h] = mn;
            ull cP = pack2(corr, corr), eP = pack2(e, e);
#pragma unroll
            for (int k = 0; k < 8; k++)
                xbarP[h][k] = fma2(eP, xnP[k], mul2(cP, xbarP[h][k]));
        }
    }
    __syncthreads();   // sUP reads done; its space becomes E tileB; slot1 -> tileA

    // ---- Phase E: 2 passes of 2 heads; Out rows -> slot0 tile (direct store) ----
    {
        const u32* Whi = g_Wpk + 2 * 16384;
        const u32* Wlo = g_Wpk + 2 * 16384 + 8192;
#pragma unroll
        for (int p = 0; p < 2; p++) {
            // pack xbar tiles for heads 2p, 2p+1
#pragma unroll
            for (int hh = 0; hh < 2; hh++) {
                int h = 2 * p + hh;
                float inv = 1.0f / s_run[h];
                ull iP = pack2(inv, inv);
                u32* EH = (u32*)(sm + SM_S1 + hh * 5120);
                u32* EL = EH + 2560;
#pragma unroll
                for (int k = 0; k < 8; k++) {
                    float v0, v1;
                    unpack2(mul2(iP, xbarP[h][k]), v0, v1);
                    split_store(v0, v1, EH, EL, (8 * cld + k) * PB + pld);
                }
            }
            __syncthreads();
            if (wid < 4) {
                int hh = wid >> 1;
                u32* EH = (u32*)(sm + SM_S1 + hh * 5120);
                u32* EL = EH + 2560;
                float acc[4][4] = {};
                gemm_mma(Whi, Wlo, EH, EL, 4 * p + wid, lane, g, t, 0, 8, acc);
                frag_store_tile(acc, g, t, sT0H, sT0L, 4 * p + wid);
            }
            __syncthreads();
        }
    }

    // ---- Phase F: y = proj @ Out -> gmem direct ----
    {
        const u32* Whi = g_Wpk + 3 * 16384;
        const u32* Wlo = g_Wpk + 3 * 16384 + 8192;
        float acc[4][4] = {};
        gemm_mma(Whi, Wlo, sT0H, sT0L, wid, lane, g, t, 0, 8, acc);
        float* o0 = out + ((size_t)b * C_ + 16 * wid + g) * HW_ + hw0;
        float* o8 = out + ((size_t)b * C_ + 16 * wid + g + 8) * HW_ + hw0;
#pragma unroll
        for (int nt = 0; nt < 4; nt++) {
            int px = 8 * nt + 2 * t;
            *(float2*)(o0 + px) = make_float2(acc[nt][0], acc[nt][1]);
            *(float2*)(o8 + px) = make_float2(acc[nt][2], acc[nt][3]);
        }
    }
}

extern "C" void kernel_launch(void* const* d_in, const int* in_sizes, int n_in,
                              void* d_out, int out_size) {
    const float* x    = (const float*)d_in[0];
    const float* pos  = (const float*)d_in[1];
    const float* nw   = (const float*)d_in[2];
    const float* nb   = (const float*)d_in[3];
    const float* qkvw = (const float*)d_in[4];
    const float* pw   = (const float*)d_in[5];
    float* out = (float*)d_out;

    reduce_kernel<<<NBT * NCHUNK, 256>>>(x, pos);
    finalize_kernel<<<1, 256>>>(pos, nw, nb);
    wprep_kernel<<<32, 256>>>(qkvw, pw);
    cudaFuncSetAttribute(main_kernel, cudaFuncAttributeMaxDynamicSharedMemorySize, SMEM_BYTES);
    main_kernel<<<B_ * NTILE, 256, SMEM_BYTES>>>(x, out);
}

// round 12
// speedup vs baseline: 1.4697x; 1.0342x over previous
#include <cuda_runtime.h>
#include <cuda_bf16.h>
#include <math.h>
#include <cstdint>

#define B_ 4
#define T_ 8
#define C_ 128
#define HW_ 9216
#define NBT 32
#define NCHUNK 72
#define CHUNK 16384
#define TILEP 32
#define NTILE 288

typedef unsigned long long ull;
typedef unsigned int u32;

__device__ __forceinline__ ull pack2(float a, float b) {
    ull r; asm("mov.b64 %0,{%1,%2};" : "=l"(r) : "f"(a), "f"(b)); return r;
}
__device__ __forceinline__ void unpack2(ull v, float& a, float& b) {
    asm("mov.b64 {%0,%1},%2;" : "=f"(a), "=f"(b) : "l"(v));
}
__device__ __forceinline__ ull fma2(ull a, ull b, ull c) {
    ull d; asm("fma.rn.f32x2 %0,%1,%2,%3;" : "=l"(d) : "l"(a), "l"(b), "l"(c)); return d;
}
__device__ __forceinline__ ull mul2(ull a, ull b) {
    ull d; asm("mul.rn.f32x2 %0,%1,%2;" : "=l"(d) : "l"(a), "l"(b)); return d;
}

// hi/lo bf16 split of two floats -> two b32 planes
__device__ __forceinline__ void split_store(float v0, float v1, u32* H, u32* L, int idx) {
    __nv_bfloat16 h0 = __float2bfloat16(v0);
    __nv_bfloat16 h1 = __float2bfloat16(v1);
    float r0 = v0 - __bfloat162float(h0);
    float r1 = v1 - __bfloat162float(h1);
    __nv_bfloat162 hh; hh.x = h0; hh.y = h1;
    __nv_bfloat162 llv; llv.x = __float2bfloat16(r0); llv.y = __float2bfloat16(r1);
    H[idx] = *(u32*)&hh;
    L[idx] = *(u32*)&llv;
}
__device__ __forceinline__ void split_pair(float v0, float v1, u32& h, u32& l) {
    __nv_bfloat16 h0 = __float2bfloat16(v0);
    __nv_bfloat16 h1 = __float2bfloat16(v1);
    float r0 = v0 - __bfloat162float(h0);
    float r1 = v1 - __bfloat162float(h1);
    __nv_bfloat162 hh; hh.x = h0; hh.y = h1;
    __nv_bfloat162 llv; llv.x = __float2bfloat16(r0); llv.y = __float2bfloat16(r1);
    h = *(u32*)&hh; l = *(u32*)&llv;
}

// m16n8k16 row.col f32.bf16.bf16.f32
__device__ __forceinline__ void mma16816(float c[4], const u32 a[4], const u32 b[2]) {
    asm volatile("mma.sync.aligned.m16n8k16.row.col.f32.bf16.bf16.f32 "
                 "{%0,%1,%2,%3},{%4,%5,%6,%7},{%8,%9},{%0,%1,%2,%3};"
                 : "+f"(c[0]), "+f"(c[1]), "+f"(c[2]), "+f"(c[3])
                 : "r"(a[0]), "r"(a[1]), "r"(a[2]), "r"(a[3]), "r"(b[0]), "r"(b[1]));
}

// deterministic scratch
__device__ float g_psum[NBT * NCHUNK];
__device__ float g_psq [NBT * NCHUNK];
__device__ float g_A[NBT * C_];
__device__ float g_Bc[NBT * C_];
// fragment-order weights: [mat][plane hi/lo][w16][ks][lane][4 u32]
__device__ u32 g_Wpk[4 * 16384];

// ---------------- Kernel 1: partial sums ----------------
__global__ __launch_bounds__(256) void reduce_kernel(const float* __restrict__ x,
                                                     const float* __restrict__ pos) {
    int bt = blockIdx.x / NCHUNK, chunk = blockIdx.x % NCHUNK, t = bt & (T_ - 1);
    const float4* x4 = (const float4*)(x + (size_t)bt * C_ * HW_);
    int base4 = chunk * (CHUNK / 4);
    float s = 0.f, sq = 0.f;
#pragma unroll
    for (int i = 0; i < 16; i++) {
        int e4 = base4 + i * 256 + threadIdx.x;
        int c = e4 / 2304;
        float pv = pos[t * C_ + c];
        float4 v = x4[e4];
        float a0 = v.x + pv, a1 = v.y + pv, a2 = v.z + pv, a3 = v.w + pv;
        s += (a0 + a1) + (a2 + a3);
        sq += (a0 * a0 + a1 * a1) + (a2 * a2 + a3 * a3);
    }
    __shared__ float ss[8], ssq[8];
#pragma unroll
    for (int o = 16; o; o >>= 1) {
        s += __shfl_down_sync(0xFFFFFFFFu, s, o);
        sq += __shfl_down_sync(0xFFFFFFFFu, sq, o);
    }
    int w = threadIdx.x >> 5;
    if ((threadIdx.x & 31) == 0) { ss[w] = s; ssq[w] = sq; }
    __syncthreads();
    if (threadIdx.x == 0) {
        float S = 0.f, SQ = 0.f;
#pragma unroll
        for (int i = 0; i < 8; i++) { S += ss[i]; SQ += ssq[i]; }
        g_psum[bt * NCHUNK + chunk] = S;
        g_psq [bt * NCHUNK + chunk] = SQ;
    }
}

// ---------------- Kernel 2: finalize ----------------
__global__ __launch_bounds__(256) void finalize_kernel(const float* __restrict__ pos,
                                                       const float* __restrict__ nw,
                                                       const float* __restrict__ nb) {
    __shared__ float sm[NBT], sr[NBT];
    int tid = threadIdx.x;
    if (tid < NBT) {
        float S = 0.f, SQ = 0.f;
        for (int i = 0; i < NCHUNK; i++) { S += g_psum[tid * NCHUNK + i]; SQ += g_psq[tid * NCHUNK + i]; }
        const float invN = 1.0f / (float)(C_ * HW_);
        float mean = S * invN;
        float var = SQ * invN - mean * mean;
        sm[tid] = mean;
        sr[tid] = rsqrtf(var + 1e-5f);
    }
    __syncthreads();
    for (int idx = tid; idx < NBT * C_; idx += 256) {
        int bt = idx >> 7, c = idx & 127, t = bt & (T_ - 1);
        float a = sr[bt] * nw[c];
        g_A[idx] = a;
        g_Bc[idx] = (pos[t * C_ + c] - sm[bt]) * a + nb[c];
    }
}

// ---------------- Kernel 2b: weight prep in fragment order ----------------
__global__ __launch_bounds__(256) void wprep_kernel(const float* __restrict__ qkv_w,
                                                    const float* __restrict__ proj_w) {
    int i = blockIdx.x * 256 + threadIdx.x;   // 0..8191
    int mat  = i >> 11;
    int rem  = i & 2047;
    int w16  = rem >> 8;
    int ks   = (rem >> 5) & 7;
    int lane = rem & 31;
    int g = lane >> 2, t = lane & 3;
    int r0 = w16 * 16 + g, r1 = r0 + 8;
    int kp0 = 8 * ks + t, kp1 = kp0 + 4;
    const float sc = 0.17677669529663687f;

    auto fetch = [&](int r, int c) -> float {
        if (mat == 0) return qkv_w[r * 128 + c];
        if (mat == 1) return qkv_w[(128 + c) * 128 + r] * sc;   // WkT (scaled)
        if (mat == 2) return qkv_w[(256 + r) * 128 + c];
        return proj_w[r * 128 + c];
    };

    u32 H[4], L[4];
    split_pair(fetch(r0, 2 * kp0), fetch(r0, 2 * kp0 + 1), H[0], L[0]);
    split_pair(fetch(r1, 2 * kp0), fetch(r1, 2 * kp0 + 1), H[1], L[1]);
    split_pair(fetch(r0, 2 * kp1), fetch(r0, 2 * kp1 + 1), H[2], L[2]);
    split_pair(fetch(r1, 2 * kp1), fetch(r1, 2 * kp1 + 1), H[3], L[3]);

    int base = mat * 16384 + ((w16 * 8 + ks) * 32 + lane) * 4;
    *(uint4*)(g_Wpk + base)        = make_uint4(H[0], H[1], H[2], H[3]);
    *(uint4*)(g_Wpk + 8192 + base) = make_uint4(L[0], L[1], L[2], L[3]);
}

// ---------------- Kernel 3: fused main ----------------
#define PB 40               // B-tile pitch (b32): conflict-free
// float-unit layout:
// [0,5120)      slot0 tile; sP ping-pong overlays [0,2048) during loop
// [5120,10240)  slot1 tile (Q output); later E tile h=0
// [10240,26624) sUP (8192 ull); later E tiles h=1..3 at 10240,15360,20480
// [26624,28672) affine AB
#define SM_S1   5120
#define SM_UP   10240
#define SM_AB   26624
#define SMEM_FLOATS 28672
#define SMEM_BYTES (SMEM_FLOATS * 4)   // 114688 = 112KB

// compensated GEMM slice with fragment-order weights
__device__ __forceinline__ void gemm_mma(const u32* __restrict__ Whi, const u32* __restrict__ Wlo,
                                         const u32* Bh, const u32* Bl,
                                         int w16, int lane, int g, int t,
                                         int ks0, int ksn, float acc[4][4]) {
#pragma unroll
    for (int ki = 0; ki < ksn; ki++) {
        int ks = ks0 + ki;
        int fi = ((w16 * 8 + ks) * 32 + lane) * 4;
        uint4 aH4 = *(const uint4*)(Whi + fi);
        uint4 aL4 = *(const uint4*)(Wlo + fi);
        u32 aH[4] = {aH4.x, aH4.y, aH4.z, aH4.w};
        u32 aL[4] = {aL4.x, aL4.y, aL4.z, aL4.w};
        int rB0 = (8 * ks + t) * PB + g;
        int rB1 = rB0 + 4 * PB;
#pragma unroll
        for (int nt = 0; nt < 4; nt++) {
            u32 bh[2] = {Bh[rB0 + 8 * nt], Bh[rB1 + 8 * nt]};
            u32 bl[2] = {Bl[rB0 + 8 * nt], Bl[rB1 + 8 * nt]};
            mma16816(acc[nt], aH, bh);
            mma16816(acc[nt], aL, bh);
            mma16816(acc[nt], aH, bl);
        }
    }
}

// shuffle-pair direct store of D fragment into a bf16 hi/lo B-tile (k2 = row/2)
__device__ __forceinline__ void frag_store_tile(const float acc[4][4], int g, int t,
                                                u32* H, u32* L, int w16) {
    int k2 = 8 * w16 + (g >> 1);
#pragma unroll
    for (int nt = 0; nt < 4; nt++) {
        float o0 = __shfl_xor_sync(0xFFFFFFFFu, acc[nt][0], 4);
        float o1 = __shfl_xor_sync(0xFFFFFFFFu, acc[nt][1], 4);
        float o2 = __shfl_xor_sync(0xFFFFFFFFu, acc[nt][2], 4);
        float o3 = __shfl_xor_sync(0xFFFFFFFFu, acc[nt][3], 4);
        int col = 8 * nt + 2 * t + (g & 1);
        float v0, v1, u0, u1;
        if ((g & 1) == 0) { v0 = acc[nt][0]; v1 = o0; u0 = acc[nt][2]; u1 = o2; }
        else              { v0 = o1; v1 = acc[nt][1]; u0 = o3; u1 = acc[nt][3]; }
        split_store(v0, v1, H, L, k2 * PB + col);
        split_store(u0, u1, H, L, (k2 + 4) * PB + col);
    }
}

// shuffle-pair direct store of D fragment into fp32-pair ull array (U)
__device__ __forceinline__ void frag_store_up(const float acc[4][4], int g, int t,
                                              ull* UP, int rowBase) {
    int c2 = g >> 1;
#pragma unroll
    for (int nt = 0; nt < 4; nt++) {
        float o0 = __shfl_xor_sync(0xFFFFFFFFu, acc[nt][0], 4);
        float o1 = __shfl_xor_sync(0xFFFFFFFFu, acc[nt][1], 4);
        float o2 = __shfl_xor_sync(0xFFFFFFFFu, acc[nt][2], 4);
        float o3 = __shfl_xor_sync(0xFFFFFFFFu, acc[nt][3], 4);
        int col = 8 * nt + 2 * t + (g & 1);
        ull lo, hi;
        if ((g & 1) == 0) { lo = pack2(acc[nt][0], o0); hi = pack2(acc[nt][2], o2); }
        else              { lo = pack2(o1, acc[nt][1]); hi = pack2(o3, acc[nt][3]); }
        UP[(rowBase + c2) * 32 + col]     = lo;
        UP[(rowBase + c2 + 4) * 32 + col] = hi;
    }
}

__global__ __launch_bounds__(256, 2) void main_kernel(const float* __restrict__ x,
                                                      float* __restrict__ out) {
    extern __shared__ float sm[];
    u32* sT0H = (u32*)sm;
    u32* sT0L = sT0H + 2560;
    u32* sS1H = (u32*)(sm + SM_S1);
    u32* sS1L = sS1H + 2560;
    ull* UPa  = (ull*)(sm + SM_UP);
    float* sAB = sm + SM_AB;

    int b    = blockIdx.x / NTILE;
    int tile = blockIdx.x % NTILE;
    int hw0  = tile * TILEP;
    int tid  = threadIdx.x;
    int wid  = tid >> 5, lane = tid & 31;
    int g    = lane >> 2, t = lane & 3;
    int cld  = wid;
    int pld  = lane;
    int c0   = cld * 16;

    // stage affine tables
    for (int idx = tid; idx < 1024; idx += 256) {
        sAB[idx]        = g_A [b * 1024 + idx];
        sAB[1024 + idx] = g_Bc[b * 1024 + idx];
    }
    // raw x7 + t0 prefetch
    float xn[16], xr[16];
    {
        const float* xb7 = x + (size_t)(b * T_ + 7) * C_ * HW_;
        const float* xb0 = x + (size_t)(b * T_) * C_ * HW_;
#pragma unroll
        for (int j = 0; j < 16; j++) xn[j] = xb7[(c0 + j) * HW_ + hw0 + pld];
#pragma unroll
        for (int j = 0; j < 16; j++) xr[j] = xb0[(c0 + j) * HW_ + hw0 + pld];
    }
    __syncthreads();

    // normalize x7; pack slot0 B tile
    {
        const float* As = sAB + 7 * 128;
        const float* Bs = sAB + 1024 + 7 * 128;
#pragma unroll
        for (int j = 0; j < 16; j++) xn[j] = xn[j] * As[c0 + j] + Bs[c0 + j];
#pragma unroll
        for (int k = 0; k < 8; k++)
            split_store(xn[2 * k], xn[2 * k + 1], sT0H, sT0L, (8 * cld + k) * PB + pld);
    }
    __syncthreads();

    // ---- Phase Q: Wq @ XN7 -> slot1 tile ----
    {
        float acc[4][4] = {};
        gemm_mma(g_Wpk, g_Wpk + 8192, sT0H, sT0L, wid, lane, g, t, 0, 8, acc);
        frag_store_tile(acc, g, t, sS1H, sS1L, wid);
    }
    __syncthreads();

    // ---- Phase U: per head h (ks {2h,2h+1}) -> sUP fp32-pairs ----
    {
        const u32* Whi = g_Wpk + 16384;
        const u32* Wlo = g_Wpk + 16384 + 8192;
#pragma unroll
        for (int h = 0; h < 4; h++) {
            float acc[4][4] = {};
            gemm_mma(Whi, Wlo, sS1H, sS1L, wid, lane, g, t, 2 * h, 2, acc);
            frag_store_up(acc, g, t, UPa, h * 64 + 8 * wid);
        }
    }
    __syncthreads();

    // ---- register-resident online softmax + xbar (U read from smem) ----
    ull xnP[8];
#pragma unroll
    for (int k = 0; k < 8; k++) xnP[k] = pack2(xn[2 * k], xn[2 * k + 1]);

    ull xbarP[4][8];
#pragma unroll
    for (int h = 0; h < 4; h++)
#pragma unroll
        for (int k = 0; k < 8; k++) xbarP[h][k] = 0ull;
    float m_run[4] = {-1e30f, -1e30f, -1e30f, -1e30f};
    float s_run[4] = {0.f, 0.f, 0.f, 0.f};

    const ull* upb = UPa + (8 * cld) * 32 + pld;   // + h*2048 + k*32

    for (int it = 0; it < T_; it++) {
        int s = (it == 0) ? (T_ - 1) : (it - 1);
        float* sPb = sm + (it & 1) * 1024;    // ping-pong partial buffer in dead slot0
        if (it > 0) {
            const float* As = sAB + s * 128;
            const float* Bs = sAB + 1024 + s * 128;
#pragma unroll
            for (int k = 0; k < 8; k++) {
                float a0 = xr[2 * k] * As[c0 + 2 * k] + Bs[c0 + 2 * k];
                float a1 = xr[2 * k + 1] * As[c0 + 2 * k + 1] + Bs[c0 + 2 * k + 1];
                xnP[k] = pack2(a0, a1);
            }
        }
        if (it >= 1 && it < T_ - 1) {
            const float* xb = x + (size_t)(b * T_ + it) * C_ * HW_;
#pragma unroll
            for (int j = 0; j < 16; j++) xr[j] = xb[(c0 + j) * HW_ + hw0 + pld];
        }
        ull lg[4] = {0ull, 0ull, 0ull, 0ull};
#pragma unroll
        for (int k = 0; k < 8; k++) {
            ull xv = xnP[k];
            lg[0] = fma2(xv, upb[0 * 2048 + k * 32], lg[0]);
            lg[1] = fma2(xv, upb[1 * 2048 + k * 32], lg[1]);
            lg[2] = fma2(xv, upb[2 * 2048 + k * 32], lg[2]);
            lg[3] = fma2(xv, upb[3 * 2048 + k * 32], lg[3]);
        }
        float4 part;
        { float lo, hi;
          unpack2(lg[0], lo, hi); part.x = lo + hi;
          unpack2(lg[1], lo, hi); part.y = lo + hi;
          unpack2(lg[2], lo, hi); part.z = lo + hi;
          unpack2(lg[3], lo, hi); part.w = lo + hi; }
        *(float4*)(sPb + (cld * 32 + pld) * 4) = part;
        __syncthreads();
        float L[4] = {0.f, 0.f, 0.f, 0.f};
#pragma unroll
        for (int k = 0; k < 8; k++) {
            float4 v = *(const float4*)(sPb + (k * 32 + pld) * 4);
            L[0] += v.x; L[1] += v.y; L[2] += v.z; L[3] += v.w;
        }
        // no trailing sync: next iter writes the other buffer
#pragma unroll
        for (int h = 0; h < 4; h++) {
            float mn = fmaxf(m_run[h], L[h]);
            float corr = __expf(m_run[h] - mn);
            float e = __expf(L[h] - mn);
            s_run[h] = s_run[h] * corr + e;
            m_run[h] = mn;
            ull cP = pack2(corr, corr), eP = pack2(e, e);
#pragma unroll
            for (int k = 0; k < 8; k++)
                xbarP[h][k] = fma2(eP, xnP[k], mul2(cP, xbarP[h][k]));
        }
    }
    __syncthreads();   // sUP reads + sP ping-pong done

    // ---- Phase E single pass: pack all 4 head tiles, all 8 warps compute ----
    {
        // E tile for head h at sm + SM_S1 + h*5120 (overlaps dead slot1/sUP)
#pragma unroll
        for (int h = 0; h < 4; h++) {
            float inv = 1.0f / s_run[h];
            ull iP = pack2(inv, inv);
            u32* EH = (u32*)(sm + SM_S1 + h * 5120);
            u32* EL = EH + 2560;
#pragma unroll
            for (int k = 0; k < 8; k++) {
                float v0, v1;
                unpack2(mul2(iP, xbarP[h][k]), v0, v1);
                split_store(v0, v1, EH, EL, (8 * cld + k) * PB + pld);
            }
        }
        __syncthreads();
        const u32* Whi = g_Wpk + 2 * 16384;
        const u32* Wlo = g_Wpk + 2 * 16384 + 8192;
        int h = wid >> 1;                      // warp w16=wid covers rows of head wid>>1
        u32* EH = (u32*)(sm + SM_S1 + h * 5120);
        u32* EL = EH + 2560;
        float acc[4][4] = {};
        gemm_mma(Whi, Wlo, EH, EL, wid, lane, g, t, 0, 8, acc);
        frag_store_tile(acc, g, t, sT0H, sT0L, wid);
    }
    __syncthreads();

    // ---- Phase F: y = proj @ Out -> gmem direct ----
    {
        const u32* Whi = g_Wpk + 3 * 16384;
        const u32* Wlo = g_Wpk + 3 * 16384 + 8192;
        float acc[4][4] = {};
        gemm_mma(Whi, Wlo, sT0H, sT0L, wid, lane, g, t, 0, 8, acc);
        float* o0 = out + ((size_t)b * C_ + 16 * wid + g) * HW_ + hw0;
        float* o8 = out + ((size_t)b * C_ + 16 * wid + g + 8) * HW_ + hw0;
#pragma unroll
        for (int nt = 0; nt < 4; nt++) {
            int px = 8 * nt + 2 * t;
            *(float2*)(o0 + px) = make_float2(acc[nt][0], acc[nt][1]);
            *(float2*)(o8 + px) = make_float2(acc[nt][2], acc[nt][3]);
        }
    }
}

extern "C" void kernel_launch(void* const* d_in, const int* in_sizes, int n_in,
                              void* d_out, int out_size) {
    const float* x    = (const float*)d_in[0];
    const float* pos  = (const float*)d_in[1];
    const float* nw   = (const float*)d_in[2];
    const float* nb   = (const float*)d_in[3];
    const float* qkvw = (const float*)d_in[4];
    const float* pw   = (const float*)d_in[5];
    float* out = (float*)d_out;

    reduce_kernel<<<NBT * NCHUNK, 256>>>(x, pos);
    finalize_kernel<<<1, 256>>>(pos, nw, nb);
    wprep_kernel<<<32, 256>>>(qkvw, pw);
    cudaFuncSetAttribute(main_kernel, cudaFuncAttributeMaxDynamicSharedMemorySize, SMEM_BYTES);
    main_kernel<<<B_ * NTILE, 256, SMEM_BYTES>>>(x, out);
}

// round 13
// speedup vs baseline: 1.5542x; 1.0575x over previous
#include <cuda_runtime.h>
#include <cuda_bf16.h>
#include <math.h>
#include <cstdint>

#define B_ 4
#define T_ 8
#define C_ 128
#define HW_ 9216
#define NBT 32
#define NCHUNK 72
#define CHUNK 16384
#define TILEP 32
#define NTILE 288

typedef unsigned long long ull;
typedef unsigned int u32;

__device__ __forceinline__ ull pack2(float a, float b) {
    ull r; asm("mov.b64 %0,{%1,%2};" : "=l"(r) : "f"(a), "f"(b)); return r;
}
__device__ __forceinline__ void unpack2(ull v, float& a, float& b) {
    asm("mov.b64 {%0,%1},%2;" : "=f"(a), "=f"(b) : "l"(v));
}
__device__ __forceinline__ ull fma2(ull a, ull b, ull c) {
    ull d; asm("fma.rn.f32x2 %0,%1,%2,%3;" : "=l"(d) : "l"(a), "l"(b), "l"(c)); return d;
}
__device__ __forceinline__ ull mul2(ull a, ull b) {
    ull d; asm("mul.rn.f32x2 %0,%1,%2;" : "=l"(d) : "l"(a), "l"(b)); return d;
}

// hi/lo bf16 split of two floats -> two b32 planes
__device__ __forceinline__ void split_store(float v0, float v1, u32* H, u32* L, int idx) {
    __nv_bfloat16 h0 = __float2bfloat16(v0);
    __nv_bfloat16 h1 = __float2bfloat16(v1);
    float r0 = v0 - __bfloat162float(h0);
    float r1 = v1 - __bfloat162float(h1);
    __nv_bfloat162 hh; hh.x = h0; hh.y = h1;
    __nv_bfloat162 llv; llv.x = __float2bfloat16(r0); llv.y = __float2bfloat16(r1);
    H[idx] = *(u32*)&hh;
    L[idx] = *(u32*)&llv;
}
__device__ __forceinline__ void split_pair(float v0, float v1, u32& h, u32& l) {
    __nv_bfloat16 h0 = __float2bfloat16(v0);
    __nv_bfloat16 h1 = __float2bfloat16(v1);
    float r0 = v0 - __bfloat162float(h0);
    float r1 = v1 - __bfloat162float(h1);
    __nv_bfloat162 hh; hh.x = h0; hh.y = h1;
    __nv_bfloat162 llv; llv.x = __float2bfloat16(r0); llv.y = __float2bfloat16(r1);
    h = *(u32*)&hh; l = *(u32*)&llv;
}

// m16n8k16 row.col f32.bf16.bf16.f32
__device__ __forceinline__ void mma16816(float c[4], const u32 a[4], const u32 b[2]) {
    asm volatile("mma.sync.aligned.m16n8k16.row.col.f32.bf16.bf16.f32 "
                 "{%0,%1,%2,%3},{%4,%5,%6,%7},{%8,%9},{%0,%1,%2,%3};"
                 : "+f"(c[0]), "+f"(c[1]), "+f"(c[2]), "+f"(c[3])
                 : "r"(a[0]), "r"(a[1]), "r"(a[2]), "r"(a[3]), "r"(b[0]), "r"(b[1]));
}

// deterministic scratch
__device__ float g_psum[NBT * NCHUNK];
__device__ float g_psq [NBT * NCHUNK];
__device__ float g_A[NBT * C_];
__device__ float g_Bc[NBT * C_];
// fragment-order weights: [mat][plane hi/lo][w16][ks][lane][4 u32]
__device__ u32 g_Wpk[4 * 16384];

// ---------------- Kernel 1: partial sums ----------------
__global__ __launch_bounds__(256) void reduce_kernel(const float* __restrict__ x,
                                                     const float* __restrict__ pos) {
    int bt = blockIdx.x / NCHUNK, chunk = blockIdx.x % NCHUNK, t = bt & (T_ - 1);
    const float4* x4 = (const float4*)(x + (size_t)bt * C_ * HW_);
    int base4 = chunk * (CHUNK / 4);
    float s = 0.f, sq = 0.f;
#pragma unroll
    for (int i = 0; i < 16; i++) {
        int e4 = base4 + i * 256 + threadIdx.x;
        int c = e4 / 2304;
        float pv = pos[t * C_ + c];
        float4 v = x4[e4];
        float a0 = v.x + pv, a1 = v.y + pv, a2 = v.z + pv, a3 = v.w + pv;
        s += (a0 + a1) + (a2 + a3);
        sq += (a0 * a0 + a1 * a1) + (a2 * a2 + a3 * a3);
    }
    __shared__ float ss[8], ssq[8];
#pragma unroll
    for (int o = 16; o; o >>= 1) {
        s += __shfl_down_sync(0xFFFFFFFFu, s, o);
        sq += __shfl_down_sync(0xFFFFFFFFu, sq, o);
    }
    int w = threadIdx.x >> 5;
    if ((threadIdx.x & 31) == 0) { ss[w] = s; ssq[w] = sq; }
    __syncthreads();
    if (threadIdx.x == 0) {
        float S = 0.f, SQ = 0.f;
#pragma unroll
        for (int i = 0; i < 8; i++) { S += ss[i]; SQ += ssq[i]; }
        g_psum[bt * NCHUNK + chunk] = S;
        g_psq [bt * NCHUNK + chunk] = SQ;
    }
}

// ---------------- Kernel 2: finalize ----------------
__global__ __launch_bounds__(256) void finalize_kernel(const float* __restrict__ pos,
                                                       const float* __restrict__ nw,
                                                       const float* __restrict__ nb) {
    __shared__ float sm[NBT], sr[NBT];
    int tid = threadIdx.x;
    if (tid < NBT) {
        float S = 0.f, SQ = 0.f;
        for (int i = 0; i < NCHUNK; i++) { S += g_psum[tid * NCHUNK + i]; SQ += g_psq[tid * NCHUNK + i]; }
        const float invN = 1.0f / (float)(C_ * HW_);
        float mean = S * invN;
        float var = SQ * invN - mean * mean;
        sm[tid] = mean;
        sr[tid] = rsqrtf(var + 1e-5f);
    }
    __syncthreads();
    for (int idx = tid; idx < NBT * C_; idx += 256) {
        int bt = idx >> 7, c = idx & 127, t = bt & (T_ - 1);
        float a = sr[bt] * nw[c];
        g_A[idx] = a;
        g_Bc[idx] = (pos[t * C_ + c] - sm[bt]) * a + nb[c];
    }
}

// ---------------- Kernel 2b: weight prep in fragment order ----------------
__global__ __launch_bounds__(256) void wprep_kernel(const float* __restrict__ qkv_w,
                                                    const float* __restrict__ proj_w) {
    int i = blockIdx.x * 256 + threadIdx.x;   // 0..8191
    int mat  = i >> 11;
    int rem  = i & 2047;
    int w16  = rem >> 8;
    int ks   = (rem >> 5) & 7;
    int lane = rem & 31;
    int g = lane >> 2, t = lane & 3;
    int r0 = w16 * 16 + g, r1 = r0 + 8;
    int kp0 = 8 * ks + t, kp1 = kp0 + 4;
    const float sc = 0.17677669529663687f;

    auto fetch = [&](int r, int c) -> float {
        if (mat == 0) return qkv_w[r * 128 + c];
        if (mat == 1) return qkv_w[(128 + c) * 128 + r] * sc;   // WkT (scaled)
        if (mat == 2) return qkv_w[(256 + r) * 128 + c];
        return proj_w[r * 128 + c];
    };

    u32 H[4], L[4];
    split_pair(fetch(r0, 2 * kp0), fetch(r0, 2 * kp0 + 1), H[0], L[0]);
    split_pair(fetch(r1, 2 * kp0), fetch(r1, 2 * kp0 + 1), H[1], L[1]);
    split_pair(fetch(r0, 2 * kp1), fetch(r0, 2 * kp1 + 1), H[2], L[2]);
    split_pair(fetch(r1, 2 * kp1), fetch(r1, 2 * kp1 + 1), H[3], L[3]);

    int base = mat * 16384 + ((w16 * 8 + ks) * 32 + lane) * 4;
    *(uint4*)(g_Wpk + base)        = make_uint4(H[0], H[1], H[2], H[3]);
    *(uint4*)(g_Wpk + 8192 + base) = make_uint4(L[0], L[1], L[2], L[3]);
}

// ---------------- Kernel 3: fused main ----------------
#define PB 40               // B-tile pitch (b32): conflict-free
// float-unit layout:
// [0,5120)      slot0 tile; sP ping-pong (2 x 2048) overlays during loop
// [5120,10240)  slot1 tile (Q output); later E tile h=0
// [10240,26624) sUP (8192 ull); later E tiles h=1..3
// [26624,28672) affine AB
#define SM_S1   5120
#define SM_UP   10240
#define SM_AB   26624
#define SMEM_FLOATS 28672
#define SMEM_BYTES (SMEM_FLOATS * 4)   // 114688 = 112KB

// compensated GEMM slice with fragment-order weights
__device__ __forceinline__ void gemm_mma(const u32* __restrict__ Whi, const u32* __restrict__ Wlo,
                                         const u32* Bh, const u32* Bl,
                                         int w16, int lane, int g, int t,
                                         int ks0, int ksn, float acc[4][4]) {
#pragma unroll
    for (int ki = 0; ki < ksn; ki++) {
        int ks = ks0 + ki;
        int fi = ((w16 * 8 + ks) * 32 + lane) * 4;
        uint4 aH4 = *(const uint4*)(Whi + fi);
        uint4 aL4 = *(const uint4*)(Wlo + fi);
        u32 aH[4] = {aH4.x, aH4.y, aH4.z, aH4.w};
        u32 aL[4] = {aL4.x, aL4.y, aL4.z, aL4.w};
        int rB0 = (8 * ks + t) * PB + g;
        int rB1 = rB0 + 4 * PB;
#pragma unroll
        for (int nt = 0; nt < 4; nt++) {
            u32 bh[2] = {Bh[rB0 + 8 * nt], Bh[rB1 + 8 * nt]};
            u32 bl[2] = {Bl[rB0 + 8 * nt], Bl[rB1 + 8 * nt]};
            mma16816(acc[nt], aH, bh);
            mma16816(acc[nt], aL, bh);
            mma16816(acc[nt], aH, bl);
        }
    }
}

// shuffle-pair direct store of D fragment into a bf16 hi/lo B-tile (k2 = row/2)
__device__ __forceinline__ void frag_store_tile(const float acc[4][4], int g, int t,
                                                u32* H, u32* L, int w16) {
    int k2 = 8 * w16 + (g >> 1);
#pragma unroll
    for (int nt = 0; nt < 4; nt++) {
        float o0 = __shfl_xor_sync(0xFFFFFFFFu, acc[nt][0], 4);
        float o1 = __shfl_xor_sync(0xFFFFFFFFu, acc[nt][1], 4);
        float o2 = __shfl_xor_sync(0xFFFFFFFFu, acc[nt][2], 4);
        float o3 = __shfl_xor_sync(0xFFFFFFFFu, acc[nt][3], 4);
        int col = 8 * nt + 2 * t + (g & 1);
        float v0, v1, u0, u1;
        if ((g & 1) == 0) { v0 = acc[nt][0]; v1 = o0; u0 = acc[nt][2]; u1 = o2; }
        else              { v0 = o1; v1 = acc[nt][1]; u0 = o3; u1 = acc[nt][3]; }
        split_store(v0, v1, H, L, k2 * PB + col);
        split_store(u0, u1, H, L, (k2 + 4) * PB + col);
    }
}

// shuffle-pair direct store of D fragment into fp32-pair ull array (U)
__device__ __forceinline__ void frag_store_up(const float acc[4][4], int g, int t,
                                              ull* UP, int rowBase) {
    int c2 = g >> 1;
#pragma unroll
    for (int nt = 0; nt < 4; nt++) {
        float o0 = __shfl_xor_sync(0xFFFFFFFFu, acc[nt][0], 4);
        float o1 = __shfl_xor_sync(0xFFFFFFFFu, acc[nt][1], 4);
        float o2 = __shfl_xor_sync(0xFFFFFFFFu, acc[nt][2], 4);
        float o3 = __shfl_xor_sync(0xFFFFFFFFu, acc[nt][3], 4);
        int col = 8 * nt + 2 * t + (g & 1);
        ull lo, hi;
        if ((g & 1) == 0) { lo = pack2(acc[nt][0], o0); hi = pack2(acc[nt][2], o2); }
        else              { lo = pack2(o1, acc[nt][1]); hi = pack2(o3, acc[nt][3]); }
        UP[(rowBase + c2) * 32 + col]     = lo;
        UP[(rowBase + c2 + 4) * 32 + col] = hi;
    }
}

__global__ __launch_bounds__(256, 2) void main_kernel(const float* __restrict__ x,
                                                      float* __restrict__ out) {
    extern __shared__ float sm[];
    u32* sT0H = (u32*)sm;
    u32* sT0L = sT0H + 2560;
    u32* sS1H = (u32*)(sm + SM_S1);
    u32* sS1L = sS1H + 2560;
    ull* UPa  = (ull*)(sm + SM_UP);
    float* sAB = sm + SM_AB;

    int b    = blockIdx.x / NTILE;
    int tile = blockIdx.x % NTILE;
    int hw0  = tile * TILEP;
    int tid  = threadIdx.x;
    int wid  = tid >> 5, lane = tid & 31;
    int g    = lane >> 2, t = lane & 3;
    int cld  = wid;
    int pld  = lane;
    int c0   = cld * 16;

    // stage affine tables
    for (int idx = tid; idx < 1024; idx += 256) {
        sAB[idx]        = g_A [b * 1024 + idx];
        sAB[1024 + idx] = g_Bc[b * 1024 + idx];
    }
    // raw x7 + t0 prefetch
    float xn[16], xr[16];
    {
        const float* xb7 = x + (size_t)(b * T_ + 7) * C_ * HW_;
        const float* xb0 = x + (size_t)(b * T_) * C_ * HW_;
#pragma unroll
        for (int j = 0; j < 16; j++) xn[j] = xb7[(c0 + j) * HW_ + hw0 + pld];
#pragma unroll
        for (int j = 0; j < 16; j++) xr[j] = xb0[(c0 + j) * HW_ + hw0 + pld];
    }
    __syncthreads();

    // normalize x7; pack slot0 B tile
    {
        const float* As = sAB + 7 * 128;
        const float* Bs = sAB + 1024 + 7 * 128;
#pragma unroll
        for (int j = 0; j < 16; j++) xn[j] = xn[j] * As[c0 + j] + Bs[c0 + j];
#pragma unroll
        for (int k = 0; k < 8; k++)
            split_store(xn[2 * k], xn[2 * k + 1], sT0H, sT0L, (8 * cld + k) * PB + pld);
    }
    __syncthreads();

    // ---- Phase Q: Wq @ XN7 -> slot1 tile ----
    {
        float acc[4][4] = {};
        gemm_mma(g_Wpk, g_Wpk + 8192, sT0H, sT0L, wid, lane, g, t, 0, 8, acc);
        frag_store_tile(acc, g, t, sS1H, sS1L, wid);
    }
    __syncthreads();

    // ---- Phase U: per head h (ks {2h,2h+1}) -> sUP fp32-pairs ----
    {
        const u32* Whi = g_Wpk + 16384;
        const u32* Wlo = g_Wpk + 16384 + 8192;
#pragma unroll
        for (int h = 0; h < 4; h++) {
            float acc[4][4] = {};
            gemm_mma(Whi, Wlo, sS1H, sS1L, wid, lane, g, t, 2 * h, 2, acc);
            frag_store_up(acc, g, t, UPa, h * 64 + 8 * wid);
        }
    }
    __syncthreads();

    // ---- paired online softmax + xbar: timestep pairs (7,0),(1,2),(3,4),(5,6) ----
    ull xnA[8], xnB[8];
#pragma unroll
    for (int k = 0; k < 8; k++) xnA[k] = pack2(xn[2 * k], xn[2 * k + 1]);

    ull xbarP[4][8];
#pragma unroll
    for (int h = 0; h < 4; h++)
#pragma unroll
        for (int k = 0; k < 8; k++) xbarP[h][k] = 0ull;
    float m_run[4] = {-1e30f, -1e30f, -1e30f, -1e30f};
    float s_run[4] = {0.f, 0.f, 0.f, 0.f};

    const ull* upb = UPa + (8 * cld) * 32 + pld;   // + h*2048 + k*32

#pragma unroll
    for (int p = 0; p < 4; p++) {
        int sa = (p == 0) ? 7 : (2 * p - 1);
        int sb = 2 * p;
        float* sPbA = sm + (p & 1) * 2048;
        float* sPbB = sPbA + 1024;

        if (p == 0) {
            // xnA = xn7 (done); xnB from prefetched raw t0 in xr
            const float* As = sAB;            // s=0
            const float* Bs = sAB + 1024;
#pragma unroll
            for (int k = 0; k < 8; k++) {
                float a0 = xr[2 * k] * As[c0 + 2 * k] + Bs[c0 + 2 * k];
                float a1 = xr[2 * k + 1] * As[c0 + 2 * k + 1] + Bs[c0 + 2 * k + 1];
                xnB[k] = pack2(a0, a1);
            }
        } else {
            // issue raw loads for sb first (latency overlapped with xnA normalize)
            float rb[16];
            const float* xbS = x + (size_t)(b * T_ + sb) * C_ * HW_;
#pragma unroll
            for (int j = 0; j < 16; j++) rb[j] = xbS[(c0 + j) * HW_ + hw0 + pld];
            // xnA from prefetched raw sa in xr
            const float* Asa = sAB + sa * 128;
            const float* Bsa = sAB + 1024 + sa * 128;
#pragma unroll
            for (int k = 0; k < 8; k++) {
                float a0 = xr[2 * k] * Asa[c0 + 2 * k] + Bsa[c0 + 2 * k];
                float a1 = xr[2 * k + 1] * Asa[c0 + 2 * k + 1] + Bsa[c0 + 2 * k + 1];
                xnA[k] = pack2(a0, a1);
            }
            const float* Asb = sAB + sb * 128;
            const float* Bsb = sAB + 1024 + sb * 128;
#pragma unroll
            for (int k = 0; k < 8; k++) {
                float a0 = rb[2 * k] * Asb[c0 + 2 * k] + Bsb[c0 + 2 * k];
                float a1 = rb[2 * k + 1] * Asb[c0 + 2 * k + 1] + Bsb[c0 + 2 * k + 1];
                xnB[k] = pack2(a0, a1);
            }
        }
        // prefetch next pair's a-raw (s = 2p+1)
        if (p < 3) {
            const float* xbN = x + (size_t)(b * T_ + 2 * p + 1) * C_ * HW_;
#pragma unroll
            for (int j = 0; j < 16; j++) xr[j] = xbN[(c0 + j) * HW_ + hw0 + pld];
        }

        // single U pass, both timesteps
        ull lgA[4] = {0ull, 0ull, 0ull, 0ull};
        ull lgB[4] = {0ull, 0ull, 0ull, 0ull};
#pragma unroll
        for (int k = 0; k < 8; k++) {
            ull xa = xnA[k], xb2 = xnB[k];
            ull u0 = upb[0 * 2048 + k * 32];
            ull u1 = upb[1 * 2048 + k * 32];
            ull u2 = upb[2 * 2048 + k * 32];
            ull u3 = upb[3 * 2048 + k * 32];
            lgA[0] = fma2(xa, u0, lgA[0]);  lgB[0] = fma2(xb2, u0, lgB[0]);
            lgA[1] = fma2(xa, u1, lgA[1]);  lgB[1] = fma2(xb2, u1, lgB[1]);
            lgA[2] = fma2(xa, u2, lgA[2]);  lgB[2] = fma2(xb2, u2, lgB[2]);
            lgA[3] = fma2(xa, u3, lgA[3]);  lgB[3] = fma2(xb2, u3, lgB[3]);
        }
        float4 pA, pBv;
        { float lo, hi;
          unpack2(lgA[0], lo, hi); pA.x = lo + hi;
          unpack2(lgA[1], lo, hi); pA.y = lo + hi;
          unpack2(lgA[2], lo, hi); pA.z = lo + hi;
          unpack2(lgA[3], lo, hi); pA.w = lo + hi;
          unpack2(lgB[0], lo, hi); pBv.x = lo + hi;
          unpack2(lgB[1], lo, hi); pBv.y = lo + hi;
          unpack2(lgB[2], lo, hi); pBv.z = lo + hi;
          unpack2(lgB[3], lo, hi); pBv.w = lo + hi; }
        *(float4*)(sPbA + (cld * 32 + pld) * 4) = pA;
        *(float4*)(sPbB + (cld * 32 + pld) * 4) = pBv;
        __syncthreads();
        float LA[4] = {0.f, 0.f, 0.f, 0.f};
        float LB[4] = {0.f, 0.f, 0.f, 0.f};
#pragma unroll
        for (int k = 0; k < 8; k++) {
            float4 vA = *(const float4*)(sPbA + (k * 32 + pld) * 4);
            float4 vB = *(const float4*)(sPbB + (k * 32 + pld) * 4);
            LA[0] += vA.x; LA[1] += vA.y; LA[2] += vA.z; LA[3] += vA.w;
            LB[0] += vB.x; LB[1] += vB.y; LB[2] += vB.z; LB[3] += vB.w;
        }
        // no trailing sync (ping-pong)

        // fused double online-softmax update
#pragma unroll
        for (int h = 0; h < 4; h++) {
            float m1 = fmaxf(m_run[h], LA[h]);
            float cA = __expf(m_run[h] - m1);
            float eA = __expf(LA[h] - m1);
            float m2 = fmaxf(m1, LB[h]);
            float cB = __expf(m1 - m2);
            float eB = __expf(LB[h] - m2);
            s_run[h] = (s_run[h] * cA + eA) * cB + eB;
            m_run[h] = m2;
            float cc = cA * cB, ea = eA * cB;
            ull ccP = pack2(cc, cc), eaP = pack2(ea, ea), ebP = pack2(eB, eB);
#pragma unroll
            for (int k = 0; k < 8; k++)
                xbarP[h][k] = fma2(ebP, xnB[k], fma2(eaP, xnA[k], mul2(ccP, xbarP[h][k])));
        }
    }
    __syncthreads();   // sUP reads + sP ping-pong done

    // ---- Phase E single pass: pack all 4 head tiles, all 8 warps compute ----
    {
#pragma unroll
        for (int h = 0; h < 4; h++) {
            float inv = 1.0f / s_run[h];
            ull iP = pack2(inv, inv);
            u32* EH = (u32*)(sm + SM_S1 + h * 5120);
            u32* EL = EH + 2560;
#pragma unroll
            for (int k = 0; k < 8; k++) {
                float v0, v1;
                unpack2(mul2(iP, xbarP[h][k]), v0, v1);
                split_store(v0, v1, EH, EL, (8 * cld + k) * PB + pld);
            }
        }
        __syncthreads();
        const u32* Whi = g_Wpk + 2 * 16384;
        const u32* Wlo = g_Wpk + 2 * 16384 + 8192;
        int h = wid >> 1;
        u32* EH = (u32*)(sm + SM_S1 + h * 5120);
        u32* EL = EH + 2560;
        float acc[4][4] = {};
        gemm_mma(Whi, Wlo, EH, EL, wid, lane, g, t, 0, 8, acc);
        frag_store_tile(acc, g, t, sT0H, sT0L, wid);
    }
    __syncthreads();

    // ---- Phase F: y = proj @ Out -> gmem direct ----
    {
        const u32* Whi = g_Wpk + 3 * 16384;
        const u32* Wlo = g_Wpk + 3 * 16384 + 8192;
        float acc[4][4] = {};
        gemm_mma(Whi, Wlo, sT0H, sT0L, wid, lane, g, t, 0, 8, acc);
        float* o0 = out + ((size_t)b * C_ + 16 * wid + g) * HW_ + hw0;
        float* o8 = out + ((size_t)b * C_ + 16 * wid + g + 8) * HW_ + hw0;
#pragma unroll
        for (int nt = 0; nt < 4; nt++) {
            int px = 8 * nt + 2 * t;
            *(float2*)(o0 + px) = make_float2(acc[nt][0], acc[nt][1]);
            *(float2*)(o8 + px) = make_float2(acc[nt][2], acc[nt][3]);
        }
    }
}

extern "C" void kernel_launch(void* const* d_in, const int* in_sizes, int n_in,
                              void* d_out, int out_size) {
    const float* x    = (const float*)d_in[0];
    const float* pos  = (const float*)d_in[1];
    const float* nw   = (const float*)d_in[2];
    const float* nb   = (const float*)d_in[3];
    const float* qkvw = (const float*)d_in[4];
    const float* pw   = (const float*)d_in[5];
    float* out = (float*)d_out;

    reduce_kernel<<<NBT * NCHUNK, 256>>>(x, pos);
    finalize_kernel<<<1, 256>>>(pos, nw, nb);
    wprep_kernel<<<32, 256>>>(qkvw, pw);
    cudaFuncSetAttribute(main_kernel, cudaFuncAttributeMaxDynamicSharedMemorySize, SMEM_BYTES);
    main_kernel<<<B_ * NTILE, 256, SMEM_BYTES>>>(x, out);
}

// round 14
// speedup vs baseline: 1.5794x; 1.0162x over previous
#include <cuda_runtime.h>
#include <cuda_bf16.h>
#include <math.h>
#include <cstdint>

#define B_ 4
#define T_ 8
#define C_ 128
#define HW_ 9216
#define NBT 32
#define NCHUNK 72
#define CHUNK 16384
#define TILEP 32
#define NTILE 288

typedef unsigned long long ull;
typedef unsigned int u32;

__device__ __forceinline__ ull pack2(float a, float b) {
    ull r; asm("mov.b64 %0,{%1,%2};" : "=l"(r) : "f"(a), "f"(b)); return r;
}
__device__ __forceinline__ void unpack2(ull v, float& a, float& b) {
    asm("mov.b64 {%0,%1},%2;" : "=f"(a), "=f"(b) : "l"(v));
}
__device__ __forceinline__ ull fma2(ull a, ull b, ull c) {
    ull d; asm("fma.rn.f32x2 %0,%1,%2,%3;" : "=l"(d) : "l"(a), "l"(b), "l"(c)); return d;
}
__device__ __forceinline__ ull mul2(ull a, ull b) {
    ull d; asm("mul.rn.f32x2 %0,%1,%2;" : "=l"(d) : "l"(a), "l"(b)); return d;
}

// hi/lo bf16 split of two floats -> two b32
__device__ __forceinline__ void split_pair(float v0, float v1, u32& h, u32& l) {
    __nv_bfloat16 h0 = __float2bfloat16(v0);
    __nv_bfloat16 h1 = __float2bfloat16(v1);
    float r0 = v0 - __bfloat162float(h0);
    float r1 = v1 - __bfloat162float(h1);
    __nv_bfloat162 hh; hh.x = h0; hh.y = h1;
    __nv_bfloat162 llv; llv.x = __float2bfloat16(r0); llv.y = __float2bfloat16(r1);
    h = *(u32*)&hh; l = *(u32*)&llv;
}

// m16n8k16 row.col f32.bf16.bf16.f32
__device__ __forceinline__ void mma16816(float c[4], const u32 a[4], const u32 b[2]) {
    asm volatile("mma.sync.aligned.m16n8k16.row.col.f32.bf16.bf16.f32 "
                 "{%0,%1,%2,%3},{%4,%5,%6,%7},{%8,%9},{%0,%1,%2,%3};"
                 : "+f"(c[0]), "+f"(c[1]), "+f"(c[2]), "+f"(c[3])
                 : "r"(a[0]), "r"(a[1]), "r"(a[2]), "r"(a[3]), "r"(b[0]), "r"(b[1]));
}

// deterministic scratch
__device__ float g_psum[NBT * NCHUNK];
__device__ float g_psq [NBT * NCHUNK];
__device__ float g_A[NBT * C_];
__device__ float g_Bc[NBT * C_];
// fragment-order weights: [mat][plane hi/lo][w16][ks][lane][4 u32]
__device__ u32 g_Wpk[4 * 16384];

// ---------------- Kernel 1: partial sums ----------------
__global__ __launch_bounds__(256) void reduce_kernel(const float* __restrict__ x,
                                                     const float* __restrict__ pos) {
    int bt = blockIdx.x / NCHUNK, chunk = blockIdx.x % NCHUNK, t = bt & (T_ - 1);
    const float4* x4 = (const float4*)(x + (size_t)bt * C_ * HW_);
    int base4 = chunk * (CHUNK / 4);
    float s = 0.f, sq = 0.f;
#pragma unroll
    for (int i = 0; i < 16; i++) {
        int e4 = base4 + i * 256 + threadIdx.x;
        int c = e4 / 2304;
        float pv = pos[t * C_ + c];
        float4 v = x4[e4];
        float a0 = v.x + pv, a1 = v.y + pv, a2 = v.z + pv, a3 = v.w + pv;
        s += (a0 + a1) + (a2 + a3);
        sq += (a0 * a0 + a1 * a1) + (a2 * a2 + a3 * a3);
    }
    __shared__ float ss[8], ssq[8];
#pragma unroll
    for (int o = 16; o; o >>= 1) {
        s += __shfl_down_sync(0xFFFFFFFFu, s, o);
        sq += __shfl_down_sync(0xFFFFFFFFu, sq, o);
    }
    int w = threadIdx.x >> 5;
    if ((threadIdx.x & 31) == 0) { ss[w] = s; ssq[w] = sq; }
    __syncthreads();
    if (threadIdx.x == 0) {
        float S = 0.f, SQ = 0.f;
#pragma unroll
        for (int i = 0; i < 8; i++) { S += ss[i]; SQ += ssq[i]; }
        g_psum[bt * NCHUNK + chunk] = S;
        g_psq [bt * NCHUNK + chunk] = SQ;
    }
}

// ---------------- Kernel 2: finalize ----------------
__global__ __launch_bounds__(256) void finalize_kernel(const float* __restrict__ pos,
                                                       const float* __restrict__ nw,
                                                       const float* __restrict__ nb) {
    __shared__ float sm[NBT], sr[NBT];
    int tid = threadIdx.x;
    if (tid < NBT) {
        float S = 0.f, SQ = 0.f;
        for (int i = 0; i < NCHUNK; i++) { S += g_psum[tid * NCHUNK + i]; SQ += g_psq[tid * NCHUNK + i]; }
        const float invN = 1.0f / (float)(C_ * HW_);
        float mean = S * invN;
        float var = SQ * invN - mean * mean;
        sm[tid] = mean;
        sr[tid] = rsqrtf(var + 1e-5f);
    }
    __syncthreads();
    for (int idx = tid; idx < NBT * C_; idx += 256) {
        int bt = idx >> 7, c = idx & 127, t = bt & (T_ - 1);
        float a = sr[bt] * nw[c];
        g_A[idx] = a;
        g_Bc[idx] = (pos[t * C_ + c] - sm[bt]) * a + nb[c];
    }
}

// ---------------- Kernel 2b: weight prep in fragment order ----------------
__global__ __launch_bounds__(256) void wprep_kernel(const float* __restrict__ qkv_w,
                                                    const float* __restrict__ proj_w) {
    int i = blockIdx.x * 256 + threadIdx.x;   // 0..8191
    int mat  = i >> 11;
    int rem  = i & 2047;
    int w16  = rem >> 8;
    int ks   = (rem >> 5) & 7;
    int lane = rem & 31;
    int g = lane >> 2, t = lane & 3;
    int r0 = w16 * 16 + g, r1 = r0 + 8;
    int kp0 = 8 * ks + t, kp1 = kp0 + 4;
    const float sc = 0.17677669529663687f;

    auto fetch = [&](int r, int c) -> float {
        if (mat == 0) return qkv_w[r * 128 + c];
        if (mat == 1) return qkv_w[(128 + c) * 128 + r] * sc;   // WkT (scaled)
        if (mat == 2) return qkv_w[(256 + r) * 128 + c];
        return proj_w[r * 128 + c];
    };

    u32 H[4], L[4];
    split_pair(fetch(r0, 2 * kp0), fetch(r0, 2 * kp0 + 1), H[0], L[0]);
    split_pair(fetch(r1, 2 * kp0), fetch(r1, 2 * kp0 + 1), H[1], L[1]);
    split_pair(fetch(r0, 2 * kp1), fetch(r0, 2 * kp1 + 1), H[2], L[2]);
    split_pair(fetch(r1, 2 * kp1), fetch(r1, 2 * kp1 + 1), H[3], L[3]);

    int base = mat * 16384 + ((w16 * 8 + ks) * 32 + lane) * 4;
    *(uint4*)(g_Wpk + base)        = make_uint4(H[0], H[1], H[2], H[3]);
    *(uint4*)(g_Wpk + 8192 + base) = make_uint4(L[0], L[1], L[2], L[3]);
}

// ---------------- Kernel 3: fused main ----------------
// B-tile format: uint4 elements {hi(k2), lo(k2), hi(k2+4), lo(k2+4)} at
// [ri*P4 + px] where ri = (k2>>3)*4 + (k2&3), k2 = c-pair row 0..63 (half-rows paired).
#define P4 34               // uint4 pitch: 34 % 8 == 2 -> conflict-free fragment reads
#define TILE4 (32 * P4)     // 1088 uint4 = 4352 floats per tile
// float-unit layout:
// [0,4352)        slot0 tile; sP ping-pong (2 x 1024 float4-groups) overlays [0,4096)
// [4352,8704)     slot1 tile (Q output); E tiles h=0..3 at 4352 + h*4352 (overlay sUP)
// [8704,25088)    sUP (8192 ull fp32-pairs)
// [25088,27136)   affine AB
#define SM_S1   4352
#define SM_UP   8704
#define SM_AB   25088
#define SMEM_FLOATS 27136
#define SMEM_BYTES (SMEM_FLOATS * 4)   // 108544

// compensated GEMM slice: fragment-order weights + uint4 row-pair B tiles
__device__ __forceinline__ void gemm_mma(const u32* __restrict__ Whi, const u32* __restrict__ Wlo,
                                         const uint4* __restrict__ Bt,
                                         int w16, int lane, int g, int t,
                                         int ks0, int ksn, float acc[4][4]) {
#pragma unroll
    for (int ki = 0; ki < ksn; ki++) {
        int ks = ks0 + ki;
        int fi = ((w16 * 8 + ks) * 32 + lane) * 4;
        uint4 aH4 = *(const uint4*)(Whi + fi);
        uint4 aL4 = *(const uint4*)(Wlo + fi);
        u32 aH[4] = {aH4.x, aH4.y, aH4.z, aH4.w};
        u32 aL[4] = {aL4.x, aL4.y, aL4.z, aL4.w};
        const uint4* brow = Bt + (ks * 4 + t) * P4 + g;
#pragma unroll
        for (int nt = 0; nt < 4; nt++) {
            uint4 bq = brow[8 * nt];
            u32 bh[2] = {bq.x, bq.z};
            u32 bl[2] = {bq.y, bq.w};
            mma16816(acc[nt], aH, bh);
            mma16816(acc[nt], aL, bh);
            mma16816(acc[nt], aH, bl);
        }
    }
}

// shuffle-pair direct store of D fragment into a uint4 row-pair B-tile
__device__ __forceinline__ void frag_store_tile(const float acc[4][4], int g, int t,
                                                uint4* Bt, int w16) {
    int ri = w16 * 4 + (g >> 1);   // k2 = 8*w16 + (g>>1): ks=w16, t'=g>>1
#pragma unroll
    for (int nt = 0; nt < 4; nt++) {
        float o0 = __shfl_xor_sync(0xFFFFFFFFu, acc[nt][0], 4);
        float o1 = __shfl_xor_sync(0xFFFFFFFFu, acc[nt][1], 4);
        float o2 = __shfl_xor_sync(0xFFFFFFFFu, acc[nt][2], 4);
        float o3 = __shfl_xor_sync(0xFFFFFFFFu, acc[nt][3], 4);
        int col = 8 * nt + 2 * t + (g & 1);
        float v0, v1, u0, u1;
        if ((g & 1) == 0) { v0 = acc[nt][0]; v1 = o0; u0 = acc[nt][2]; u1 = o2; }
        else              { v0 = o1; v1 = acc[nt][1]; u0 = o3; u1 = acc[nt][3]; }
        u32 vh, vl, uh, ulw;
        split_pair(v0, v1, vh, vl);
        split_pair(u0, u1, uh, ulw);
        Bt[ri * P4 + col] = make_uint4(vh, vl, uh, ulw);
    }
}

// shuffle-pair direct store of D fragment into fp32-pair ull array (U)
__device__ __forceinline__ void frag_store_up(const float acc[4][4], int g, int t,
                                              ull* UP, int rowBase) {
    int c2 = g >> 1;
#pragma unroll
    for (int nt = 0; nt < 4; nt++) {
        float o0 = __shfl_xor_sync(0xFFFFFFFFu, acc[nt][0], 4);
        float o1 = __shfl_xor_sync(0xFFFFFFFFu, acc[nt][1], 4);
        float o2 = __shfl_xor_sync(0xFFFFFFFFu, acc[nt][2], 4);
        float o3 = __shfl_xor_sync(0xFFFFFFFFu, acc[nt][3], 4);
        int col = 8 * nt + 2 * t + (g & 1);
        ull lo, hi;
        if ((g & 1) == 0) { lo = pack2(acc[nt][0], o0); hi = pack2(acc[nt][2], o2); }
        else              { lo = pack2(o1, acc[nt][1]); hi = pack2(o3, acc[nt][3]); }
        UP[(rowBase + c2) * 32 + col]     = lo;
        UP[(rowBase + c2 + 4) * 32 + col] = hi;
    }
}

__global__ __launch_bounds__(256, 2) void main_kernel(const float* __restrict__ x,
                                                      float* __restrict__ out) {
    extern __shared__ float sm[];
    uint4* sT0 = (uint4*)sm;
    uint4* sS1 = (uint4*)(sm + SM_S1);
    ull* UPa  = (ull*)(sm + SM_UP);
    float* sAB = sm + SM_AB;

    int b    = blockIdx.x / NTILE;
    int tile = blockIdx.x % NTILE;
    int hw0  = tile * TILEP;
    int tid  = threadIdx.x;
    int wid  = tid >> 5, lane = tid & 31;
    int g    = lane >> 2, t = lane & 3;
    int cld  = wid;
    int pld  = lane;
    int c0   = cld * 16;

    // stage affine tables
    for (int idx = tid; idx < 1024; idx += 256) {
        sAB[idx]        = g_A [b * 1024 + idx];
        sAB[1024 + idx] = g_Bc[b * 1024 + idx];
    }
    // raw x7 + t0 prefetch
    float xn[16], xr[16];
    {
        const float* xb7 = x + (size_t)(b * T_ + 7) * C_ * HW_;
        const float* xb0 = x + (size_t)(b * T_) * C_ * HW_;
#pragma unroll
        for (int j = 0; j < 16; j++) xn[j] = xb7[(c0 + j) * HW_ + hw0 + pld];
#pragma unroll
        for (int j = 0; j < 16; j++) xr[j] = xb0[(c0 + j) * HW_ + hw0 + pld];
    }
    __syncthreads();

    // normalize x7; pack slot0 B tile (row-pair uint4)
    {
        const float* As = sAB + 7 * 128;
        const float* Bs = sAB + 1024 + 7 * 128;
#pragma unroll
        for (int j = 0; j < 16; j++) xn[j] = xn[j] * As[c0 + j] + Bs[c0 + j];
#pragma unroll
        for (int k = 0; k < 4; k++) {
            u32 h0, l0, h1, l1;
            split_pair(xn[2 * k], xn[2 * k + 1], h0, l0);
            split_pair(xn[2 * (k + 4)], xn[2 * (k + 4) + 1], h1, l1);
            sT0[(cld * 4 + k) * P4 + pld] = make_uint4(h0, l0, h1, l1);
        }
    }
    __syncthreads();

    // ---- Phase Q: Wq @ XN7 -> slot1 tile ----
    {
        float acc[4][4] = {};
        gemm_mma(g_Wpk, g_Wpk + 8192, sT0, wid, lane, g, t, 0, 8, acc);
        frag_store_tile(acc, g, t, sS1, wid);
    }
    __syncthreads();

    // ---- Phase U: per head h (ks {2h,2h+1}) -> sUP fp32-pairs ----
    {
        const u32* Whi = g_Wpk + 16384;
        const u32* Wlo = g_Wpk + 16384 + 8192;
#pragma unroll
        for (int h = 0; h < 4; h++) {
            float acc[4][4] = {};
            gemm_mma(Whi, Wlo, sS1, wid, lane, g, t, 2 * h, 2, acc);
            frag_store_up(acc, g, t, UPa, h * 64 + 8 * wid);
        }
    }
    __syncthreads();

    // ---- paired online softmax + xbar: timestep pairs (7,0),(1,2),(3,4),(5,6) ----
    ull xnA[8], xnB[8];
#pragma unroll
    for (int k = 0; k < 8; k++) xnA[k] = pack2(xn[2 * k], xn[2 * k + 1]);

    ull xbarP[4][8];
#pragma unroll
    for (int h = 0; h < 4; h++)
#pragma unroll
        for (int k = 0; k < 8; k++) xbarP[h][k] = 0ull;
    float m_run[4] = {-1e30f, -1e30f, -1e30f, -1e30f};
    float s_run[4] = {0.f, 0.f, 0.f, 0.f};

    const ull* upb = UPa + (8 * cld) * 32 + pld;   // + h*2048 + k*32

#pragma unroll
    for (int p = 0; p < 4; p++) {
        int sa = (p == 0) ? 7 : (2 * p - 1);
        int sb = 2 * p;
        float* sPbA = sm + (p & 1) * 2048;
        float* sPbB = sPbA + 1024;

        if (p == 0) {
            const float* As = sAB;
            const float* Bs = sAB + 1024;
#pragma unroll
            for (int k = 0; k < 8; k++) {
                float a0 = xr[2 * k] * As[c0 + 2 * k] + Bs[c0 + 2 * k];
                float a1 = xr[2 * k + 1] * As[c0 + 2 * k + 1] + Bs[c0 + 2 * k + 1];
                xnB[k] = pack2(a0, a1);
            }
        } else {
            float rb[16];
            const float* xbS = x + (size_t)(b * T_ + sb) * C_ * HW_;
#pragma unroll
            for (int j = 0; j < 16; j++) rb[j] = xbS[(c0 + j) * HW_ + hw0 + pld];
            const float* Asa = sAB + sa * 128;
            const float* Bsa = sAB + 1024 + sa * 128;
#pragma unroll
            for (int k = 0; k < 8; k++) {
                float a0 = xr[2 * k] * Asa[c0 + 2 * k] + Bsa[c0 + 2 * k];
                float a1 = xr[2 * k + 1] * Asa[c0 + 2 * k + 1] + Bsa[c0 + 2 * k + 1];
                xnA[k] = pack2(a0, a1);
            }
            const float* Asb = sAB + sb * 128;
            const float* Bsb = sAB + 1024 + sb * 128;
#pragma unroll
            for (int k = 0; k < 8; k++) {
                float a0 = rb[2 * k] * Asb[c0 + 2 * k] + Bsb[c0 + 2 * k];
                float a1 = rb[2 * k + 1] * Asb[c0 + 2 * k + 1] + Bsb[c0 + 2 * k + 1];
                xnB[k] = pack2(a0, a1);
            }
        }
        if (p < 3) {
            const float* xbN = x + (size_t)(b * T_ + 2 * p + 1) * C_ * HW_;
#pragma unroll
            for (int j = 0; j < 16; j++) xr[j] = xbN[(c0 + j) * HW_ + hw0 + pld];
        }

        // single U pass, both timesteps
        ull lgA[4] = {0ull, 0ull, 0ull, 0ull};
        ull lgB[4] = {0ull, 0ull, 0ull, 0ull};
#pragma unroll
        for (int k = 0; k < 8; k++) {
            ull xa = xnA[k], xb2 = xnB[k];
            ull u0 = upb[0 * 2048 + k * 32];
            ull u1 = upb[1 * 2048 + k * 32];
            ull u2 = upb[2 * 2048 + k * 32];
            ull u3 = upb[3 * 2048 + k * 32];
            lgA[0] = fma2(xa, u0, lgA[0]);  lgB[0] = fma2(xb2, u0, lgB[0]);
            lgA[1] = fma2(xa, u1, lgA[1]);  lgB[1] = fma2(xb2, u1, lgB[1]);
            lgA[2] = fma2(xa, u2, lgA[2]);  lgB[2] = fma2(xb2, u2, lgB[2]);
            lgA[3] = fma2(xa, u3, lgA[3]);  lgB[3] = fma2(xb2, u3, lgB[3]);
        }
        float4 pA, pBv;
        { float lo, hi;
          unpack2(lgA[0], lo, hi); pA.x = lo + hi;
          unpack2(lgA[1], lo, hi); pA.y = lo + hi;
          unpack2(lgA[2], lo, hi); pA.z = lo + hi;
          unpack2(lgA[3], lo, hi); pA.w = lo + hi;
          unpack2(lgB[0], lo, hi); pBv.x = lo + hi;
          unpack2(lgB[1], lo, hi); pBv.y = lo + hi;
          unpack2(lgB[2], lo, hi); pBv.z = lo + hi;
          unpack2(lgB[3], lo, hi); pBv.w = lo + hi; }
        *(float4*)(sPbA + (cld * 32 + pld) * 4) = pA;
        *(float4*)(sPbB + (cld * 32 + pld) * 4) = pBv;
        __syncthreads();
        float LA[4] = {0.f, 0.f, 0.f, 0.f};
        float LB[4] = {0.f, 0.f, 0.f, 0.f};
#pragma unroll
        for (int k = 0; k < 8; k++) {
            float4 vA = *(const float4*)(sPbA + (k * 32 + pld) * 4);
            float4 vB = *(const float4*)(sPbB + (k * 32 + pld) * 4);
            LA[0] += vA.x; LA[1] += vA.y; LA[2] += vA.z; LA[3] += vA.w;
            LB[0] += vB.x; LB[1] += vB.y; LB[2] += vB.z; LB[3] += vB.w;
        }
        // no trailing sync (ping-pong)

        // fused double online-softmax update
#pragma unroll
        for (int h = 0; h < 4; h++) {
            float m1 = fmaxf(m_run[h], LA[h]);
            float cA = __expf(m_run[h] - m1);
            float eA = __expf(LA[h] - m1);
            float m2 = fmaxf(m1, LB[h]);
            float cB = __expf(m1 - m2);
            float eB = __expf(LB[h] - m2);
            s_run[h] = (s_run[h] * cA + eA) * cB + eB;
            m_run[h] = m2;
            float cc = cA * cB, ea = eA * cB;
            ull ccP = pack2(cc, cc), eaP = pack2(ea, ea), ebP = pack2(eB, eB);
#pragma unroll
            for (int k = 0; k < 8; k++)
                xbarP[h][k] = fma2(ebP, xnB[k], fma2(eaP, xnA[k], mul2(ccP, xbarP[h][k])));
        }
    }
    __syncthreads();   // sUP reads + sP ping-pong done

    // ---- Phase E single pass: pack all 4 head tiles, all 8 warps compute ----
    {
#pragma unroll
        for (int h = 0; h < 4; h++) {
            float inv = 1.0f / s_run[h];
            ull iP = pack2(inv, inv);
            uint4* Et = (uint4*)(sm + SM_S1 + h * 4352);
#pragma unroll
            for (int k = 0; k < 4; k++) {
                float v0, v1, u0, u1;
                unpack2(mul2(iP, xbarP[h][k]), v0, v1);
                unpack2(mul2(iP, xbarP[h][k + 4]), u0, u1);
                u32 h0, l0, h1, l1;
                split_pair(v0, v1, h0, l0);
                split_pair(u0, u1, h1, l1);
                Et[(cld * 4 + k) * P4 + pld] = make_uint4(h0, l0, h1, l1);
            }
        }
        __syncthreads();
        const u32* Whi = g_Wpk + 2 * 16384;
        const u32* Wlo = g_Wpk + 2 * 16384 + 8192;
        int h = wid >> 1;
        uint4* Et = (uint4*)(sm + SM_S1 + h * 4352);
        float acc[4][4] = {};
        gemm_mma(Whi, Wlo, Et, wid, lane, g, t, 0, 8, acc);
        frag_store_tile(acc, g, t, sT0, wid);
    }
    __syncthreads();

    // ---- Phase F: y = proj @ Out -> gmem direct ----
    {
        const u32* Whi = g_Wpk + 3 * 16384;
        const u32* Wlo = g_Wpk + 3 * 16384 + 8192;
        float acc[4][4] = {};
        gemm_mma(Whi, Wlo, sT0, wid, lane, g, t, 0, 8, acc);
        float* o0 = out + ((size_t)b * C_ + 16 * wid + g) * HW_ + hw0;
        float* o8 = out + ((size_t)b * C_ + 16 * wid + g + 8) * HW_ + hw0;
#pragma unroll
        for (int nt = 0; nt < 4; nt++) {
            int px = 8 * nt + 2 * t;
            *(float2*)(o0 + px) = make_float2(acc[nt][0], acc[nt][1]);
            *(float2*)(o8 + px) = make_float2(acc[nt][2], acc[nt][3]);
        }
    }
}

extern "C" void kernel_launch(void* const* d_in, const int* in_sizes, int n_in,
                              void* d_out, int out_size) {
    const float* x    = (const float*)d_in[0];
    const float* pos  = (const float*)d_in[1];
    const float* nw   = (const float*)d_in[2];
    const float* nb   = (const float*)d_in[3];
    const float* qkvw = (const float*)d_in[4];
    const float* pw   = (const float*)d_in[5];
    float* out = (float*)d_out;

    reduce_kernel<<<NBT * NCHUNK, 256>>>(x, pos);
    finalize_kernel<<<1, 256>>>(pos, nw, nb);
    wprep_kernel<<<32, 256>>>(qkvw, pw);
    cudaFuncSetAttribute(main_kernel, cudaFuncAttributeMaxDynamicSharedMemorySize, SMEM_BYTES);
    main_kernel<<<B_ * NTILE, 256, SMEM_BYTES>>>(x, out);
}